// round 11
// baseline (speedup 1.0000x reference)
#include <cuda_runtime.h>
#include <cuda_bf16.h>
#include <math.h>
#include <stdint.h>

// Problem constants (fixed by setup_inputs)
#define BB 64      // batch
#define CC 256     // channels
#define DD 64      // 2D map side
#define TT 128     // total sentences (B * n, n = 2)
#define PP 2080    // triu proposals
#define TPL 128    // proposals per tile (= GEMM M)
#define NTILE 17   // ceil(PP / TPL)
#define NBLK (BB * NTILE)
#define KCH 32     // K floats per chunk
#define NCHUNK (CC / KCH)  // 8
#define VR 40      // smem row stride in bf16 (80B rows; conflict-free ldmatrix)

// per buffer (bf16 elems): Vh 128*40=5120, Vl 5120, Qh 64*40=2560, Ql 2560
#define BUF_ELEMS 15360
#define DYN_SMEM (2 * BUF_ELEMS * 2)   // 61440 B

// ---------------- scratch (device globals; fully overwritten every launch) ---
__device__ int   g_pk[TT];               // argmax p (triu order) per t
__device__ int   g_pkflat[TT];           // flat r*64+c position
__device__ float g_qn[BB * CC];          // normalized query feats
__device__ __nv_bfloat16 g_qbh[BB * CC]; // bf16 hi of qn
__device__ __nv_bfloat16 g_qbl[BB * CC]; // bf16 lo of qn
__device__ float g_sn[TT * CC];          // normalized sentence feats
__device__ float g_norm2k[TT];           // |v[b', pos_k(t)]|^2
__device__ float g_cross[BB];            // vk0 . vk1 raw dot
__device__ float g_sTop[TT * BB];        // cosine(topk_vf[t], qf_n[b])
__device__ float g_qs[BB * TT];          // qf_n[b] . sf_n[t']
__device__ float g_totQpart[BB * NBLK];  // TRANSPOSED: [q][blk]
__device__ float g_totQ[BB];
__device__ float g_posQpart[NBLK];
__device__ float g_negIpart[NBLK * 2];

// ---------------- mma.sync + ldmatrix wrappers ----------------
__device__ __forceinline__ void mma16816(float* d,
                                         uint32_t a0, uint32_t a1,
                                         uint32_t a2, uint32_t a3,
                                         uint32_t b0, uint32_t b1) {
    asm volatile(
        "mma.sync.aligned.m16n8k16.row.col.f32.bf16.bf16.f32 "
        "{%0,%1,%2,%3}, {%4,%5,%6,%7}, {%8,%9}, {%0,%1,%2,%3};"
        : "+f"(d[0]), "+f"(d[1]), "+f"(d[2]), "+f"(d[3])
        : "r"(a0), "r"(a1), "r"(a2), "r"(a3), "r"(b0), "r"(b1));
}

__device__ __forceinline__ void ldsm_x4(uint32_t& r0, uint32_t& r1,
                                        uint32_t& r2, uint32_t& r3, uint32_t a) {
    asm volatile("ldmatrix.sync.aligned.m8n8.x4.shared.b16 {%0,%1,%2,%3}, [%4];"
                 : "=r"(r0), "=r"(r1), "=r"(r2), "=r"(r3) : "r"(a));
}

__device__ __forceinline__ uint32_t bf16pair(float lo, float hi) {
    __nv_bfloat162 h2(__float2bfloat16(lo), __float2bfloat16(hi));
    return *(uint32_t*)&h2;
}

// ---------------- topk (K=1) + topk-vector stats, fused per b' ----------------
__global__ void k_topkstats(const float* __restrict__ iou2ds,
                            const float* __restrict__ vid) {
    int b = blockIdx.x, tid = threadIdx.x;  // 256 threads
    __shared__ float bv[256]; __shared__ int bx[256];
    __shared__ int pkf[2];

    for (int j = 0; j < 2; j++) {
        int t = 2 * b + j;
        const float4* row = (const float4*)(iou2ds + (size_t)t * (DD * DD));
        float best = -1e30f; int bf = 0x3fffffff;
        for (int v = tid; v < 1024; v += 256) {
            float4 x = row[v];
            int f0 = v * 4;
            float vals[4] = {x.x, x.y, x.z, x.w};
            #pragma unroll
            for (int e = 0; e < 4; e++) {
                int f = f0 + e, r = f >> 6, c = f & 63;
                if (c >= r && vals[e] > best) { best = vals[e]; bf = f; }
            }
        }
        bv[tid] = best; bx[tid] = bf;
        __syncthreads();
        for (int s = 128; s > 0; s >>= 1) {
            if (tid < s) {
                if (bv[tid + s] > bv[tid] ||
                    (bv[tid + s] == bv[tid] && bx[tid + s] < bx[tid])) {
                    bv[tid] = bv[tid + s]; bx[tid] = bx[tid + s];
                }
            }
            __syncthreads();
        }
        if (tid == 0) {
            int f = bx[0], r = f >> 6, c = f & 63;
            g_pk[t] = r * 64 - (r * (r - 1)) / 2 + (c - r);
            g_pkflat[t] = f;
            pkf[j] = f;
        }
        __syncthreads();
    }

    int pk0 = pkf[0], pk1 = pkf[1];
    const float* vb = vid + (size_t)b * CC * (DD * DD);
    float v0 = vb[(size_t)tid * (DD * DD) + pk0];
    float v1 = vb[(size_t)tid * (DD * DD) + pk1];
    float a = v0 * v0, d2 = v1 * v1, x = v0 * v1;
    for (int o = 16; o > 0; o >>= 1) {
        a  += __shfl_xor_sync(0xffffffffu, a, o);
        d2 += __shfl_xor_sync(0xffffffffu, d2, o);
        x  += __shfl_xor_sync(0xffffffffu, x, o);
    }
    __shared__ float sa[8], sd[8], sx[8];
    if ((tid & 31) == 0) { sa[tid >> 5] = a; sd[tid >> 5] = d2; sx[tid >> 5] = x; }
    __syncthreads();
    if (tid == 0) {
        float ta = 0, td = 0, tc = 0;
        for (int w = 0; w < 8; w++) { ta += sa[w]; td += sd[w]; tc += sx[w]; }
        g_norm2k[2 * b] = ta; g_norm2k[2 * b + 1] = td; g_cross[b] = tc;
    }
}

// ---------------- row normalization (fused q + s) ----------------
__device__ __forceinline__ float blk_sumsq(float v) {
    float s = v * v;
    for (int o = 16; o > 0; o >>= 1) s += __shfl_xor_sync(0xffffffffu, s, o);
    __shared__ float ws[8];
    int tid = threadIdx.x;
    if ((tid & 31) == 0) ws[tid >> 5] = s;
    __syncthreads();
    return ws[0] + ws[1] + ws[2] + ws[3] + ws[4] + ws[5] + ws[6] + ws[7];
}

__global__ void k_norms(const float* __restrict__ q, const float* __restrict__ s) {
    int row = blockIdx.x, tid = threadIdx.x;
    if (row < BB) {
        float v = q[row * CC + tid];
        float inv = 1.0f / fmaxf(sqrtf(blk_sumsq(v)), 1e-12f);
        float nv = v * inv;
        g_qn[row * CC + tid] = nv;
        __nv_bfloat16 h = __float2bfloat16(nv);
        g_qbh[row * CC + tid] = h;
        g_qbl[row * CC + tid] = __float2bfloat16(nv - __bfloat162float(h));
    } else {
        int r = row - BB;
        float v = s[r * CC + tid];
        float inv = 1.0f / fmaxf(sqrtf(blk_sumsq(v)), 1e-12f);
        g_sn[r * CC + tid] = v * inv;
    }
}

// ---------------- qf_n @ sf_n^T (tiny) ----------------
__global__ void k_qs() {
    int b = blockIdx.x, tid = threadIdx.x;
    __shared__ float qsh[CC];
    qsh[tid] = g_qn[b * CC + tid];
    __syncthreads();
    int w = tid >> 5, lane = tid & 31;
    for (int t2 = w; t2 < TT; t2 += 8) {
        float a = 0.f;
        for (int c = lane; c < CC; c += 32) a += qsh[c] * g_sn[t2 * CC + c];
        for (int o = 16; o > 0; o >>= 1) a += __shfl_xor_sync(0xffffffffu, a, o);
        if (lane == 0) g_qs[b * TT + t2] = a;
    }
}

// ---------------- main fused pass: pipelined mma.sync + ldmatrix ------------
// grid (NTILE, BB), 256 threads (8 warps). Double-buffered smem tiles,
// register-prefetched gather overlapping the MMA. One barrier per chunk.
__global__ void __launch_bounds__(256, 3) k_main(const float* __restrict__ vid,
                                                 const float* __restrict__ iou2d) {
    extern __shared__ __align__(16) char dyn[];
    __nv_bfloat16* sbase = (__nv_bfloat16*)dyn;
    uint32_t sAddr = (uint32_t)__cvta_generic_to_shared(sbase);

    __shared__ float vk0s[CC], vk1s[CC];
    __shared__ int   posArr[TPL];
    __shared__ float ioul[TPL], invnS[TPL];
    __shared__ float statA[256], stat0[256], stat1[256];
    __shared__ float partQ[8][64];
    __shared__ float red[256];
    __shared__ float nb0s[TPL], nb1s[TPL];

    int tileIdx = blockIdx.x, bp = blockIdx.y;
    int p0 = tileIdx * TPL;
    int tid = threadIdx.x, wid = tid >> 5, lane = tid & 31;

    const float* vb = vid + (size_t)bp * CC * (DD * DD);
    int t0 = 2 * bp, t1 = t0 + 1;
    int pkI0 = g_pk[t0], pkI1 = g_pk[t1];
    int pf0 = g_pkflat[t0], pf1 = g_pkflat[t1];
    vk0s[tid] = vb[(size_t)tid * (DD * DD) + pf0];
    vk1s[tid] = vb[(size_t)tid * (DD * DD) + pf1];

    if (tid < TPL) {
        int pg = p0 + tid;
        int pc = pg < PP ? pg : PP - 1;  // clamp; masked in epilogue
        int r = (int)(64.5f - sqrtf(64.5f * 64.5f - 2.0f * (float)pc));
        while (r > 0  && r * 64 - (r * (r - 1)) / 2 > pc) r--;
        while (r < 63 && (r + 1) * 64 - ((r + 1) * r) / 2 <= pc) r++;
        int start = r * 64 - (r * (r - 1)) / 2;
        int pos = r * 64 + (r + (pc - start));
        posArr[tid] = pos;
        ioul[tid] = iou2d[bp * (DD * DD) + pos];
    }
    __syncthreads();

    int p = tid & 127, kh = tid >> 7;       // gather role: (proposal, k-half of 16)
    const float* gp = vb + posArr[p];
    float an = 0.f, a0 = 0.f, a1 = 0.f;

    float acc[8][4] = {};                   // 8 n-blocks x 4 f32
    int g = lane >> 2, tg = lane & 3;       // fragment group ids

    // ldmatrix per-lane address offsets (bytes)
    uint32_t aoffA = ((uint32_t)((wid * 16 + (lane & 15)) * VR) +
                      ((lane >> 4) << 3)) * 2u;
    uint32_t boffB = ((uint32_t)(((lane & 7) + ((lane & 16) ? 8 : 0)) * VR) +
                      ((lane & 8) ? 8 : 0)) * 2u;

    // prefetch chunk 0
    float pf[16];
    #pragma unroll
    for (int j = 0; j < 16; j++)
        pf[j] = gp[(size_t)(kh * 16 + j) * (DD * DD)];

    for (int c = 0; c < NCHUNK; c++) {
        int kb = c * KCH;
        int buf = c & 1;
        __nv_bfloat16* Vh = sbase + buf * BUF_ELEMS;
        __nv_bfloat16* Vl = Vh + 5120;
        __nv_bfloat16* Qh = Vh + 10240;
        __nv_bfloat16* Ql = Vh + 12800;
        uint32_t sV = sAddr + (uint32_t)buf * (BUF_ELEMS * 2u);

        // ---- convert prefetched V -> smem (hi/lo), stats ride along ----
        #pragma unroll
        for (int j = 0; j < 16; j += 4) {
            int k = kb + kh * 16 + j;
            float v0 = pf[j], v1 = pf[j + 1], v2 = pf[j + 2], v3 = pf[j + 3];
            an += v0 * v0 + v1 * v1 + v2 * v2 + v3 * v3;
            a0 += v0 * vk0s[k] + v1 * vk0s[k + 1] + v2 * vk0s[k + 2] + v3 * vk0s[k + 3];
            a1 += v0 * vk1s[k] + v1 * vk1s[k + 1] + v2 * vk1s[k + 2] + v3 * vk1s[k + 3];
            __nv_bfloat16 h0 = __float2bfloat16(v0), h1 = __float2bfloat16(v1);
            __nv_bfloat16 h2 = __float2bfloat16(v2), h3 = __float2bfloat16(v3);
            uint2 hb, lb;
            { __nv_bfloat162 t01(h0, h1), t23(h2, h3);
              hb.x = *(uint32_t*)&t01; hb.y = *(uint32_t*)&t23; }
            lb.x = bf16pair(v0 - __bfloat162float(h0), v1 - __bfloat162float(h1));
            lb.y = bf16pair(v2 - __bfloat162float(h2), v3 - __bfloat162float(h3));
            int so = p * VR + kh * 16 + j;
            *(uint2*)&Vh[so] = hb;
            *(uint2*)&Vl[so] = lb;
        }
        // ---- Q tiles: 64 q x 16 u32-pairs each, coalesced (L1-hot) ----
        #pragma unroll
        for (int i = 0; i < 4; i++) {
            int idx = tid + i * 256;          // 0..1023
            int q = idx >> 4, kp = idx & 15;
            *(uint32_t*)&Qh[q * VR + kp * 2] = *(const uint32_t*)&g_qbh[q * CC + kb + kp * 2];
            *(uint32_t*)&Ql[q * VR + kp * 2] = *(const uint32_t*)&g_qbl[q * CC + kb + kp * 2];
        }
        __syncthreads();

        // ---- issue next chunk's gather (overlaps MMA below) ----
        if (c + 1 < NCHUNK) {
            int kn = (c + 1) * KCH + kh * 16;
            #pragma unroll
            for (int j = 0; j < 16; j++)
                pf[j] = gp[(size_t)(kn + j) * (DD * DD)];
        }

        // ---- MMA via ldmatrix: warp w rows w*16.., all 64 cols, 2 k-steps --
        #pragma unroll
        for (int ks = 0; ks < 2; ks++) {
            uint32_t kadd = (uint32_t)(ks * 32);   // 16 bf16 * 2B
            uint32_t ah0, ah1, ah2, ah3, al0, al1, al2, al3;
            ldsm_x4(ah0, ah1, ah2, ah3, sV + aoffA + kadd);
            ldsm_x4(al0, al1, al2, al3, sV + aoffA + kadd + 10240u);  // Vl
            #pragma unroll
            for (int j = 0; j < 4; j++) {
                uint32_t bq = sV + 20480u + boffB + (uint32_t)(j * (16 * VR * 2)) + kadd;
                uint32_t bh0, bh1, bh2, bh3, bl0, bl1, bl2, bl3;
                ldsm_x4(bh0, bh1, bh2, bh3, bq);            // Qh
                ldsm_x4(bl0, bl1, bl2, bl3, bq + 5120u);    // Ql
                mma16816(acc[2 * j],     ah0, ah1, ah2, ah3, bh0, bh1);
                mma16816(acc[2 * j],     ah0, ah1, ah2, ah3, bl0, bl1);
                mma16816(acc[2 * j],     al0, al1, al2, al3, bh0, bh1);
                mma16816(acc[2 * j + 1], ah0, ah1, ah2, ah3, bh2, bh3);
                mma16816(acc[2 * j + 1], ah0, ah1, ah2, ah3, bl2, bl3);
                mma16816(acc[2 * j + 1], al0, al1, al2, al3, bh2, bh3);
            }
        }
        // no trailing barrier: double-buffered; LDSM results are consumed into
        // registers before this warp reaches sync(c+1).
    }

    // ---- stats combine (p owned by 2 threads: kh halves) ----
    statA[tid] = an; stat0[tid] = a0; stat1[tid] = a1;
    __syncthreads();
    if (tid < TPL) {
        float n2 = statA[tid] + statA[tid + 128];
        float inv = 1.0f / fmaxf(sqrtf(n2), 1e-12f);
        invnS[tid] = inv;
        float i0 = stat0[tid] + stat0[tid + 128];
        float i1 = stat1[tid] + stat1[tid + 128];
        bool negm = (p0 + tid < PP) && (ioul[tid] < 0.5f);
        float invk0 = 1.0f / fmaxf(sqrtf(g_norm2k[t0]), 1e-12f);
        float invk1 = 1.0f / fmaxf(sqrtf(g_norm2k[t1]), 1e-12f);
        nb0s[tid] = negm ? __expf(10.0f * i0 * inv * invk0) : 0.f;
        nb1s[tid] = negm ? __expf(10.0f * i1 * inv * invk1) : 0.f;
    }
    __syncthreads();

    // ---- epilogue: scores -> exp -> column partials ----
    int rl0 = wid * 16 + g, rl1 = rl0 + 8;
    int pg0 = p0 + rl0, pg1 = p0 + rl1;
    bool v0 = pg0 < PP, v1 = pg1 < PP;
    float in0 = invnS[rl0], in1 = invnS[rl1];
    bool pm0 = v0 && (ioul[rl0] > 0.5f), pm1 = v1 && (ioul[rl1] > 0.5f);
    bool w00 = (pg0 == pkI0), w01 = (pg0 == pkI1);
    bool w10 = (pg1 == pkI0), w11 = (pg1 == pkI1);

    float colSum[16];
    float posAcc = 0.f;
    #pragma unroll
    for (int nb = 0; nb < 8; nb++) {
        int n0 = nb * 8 + tg * 2, n1 = n0 + 1;
        float s00 = acc[nb][0] * in0, s01 = acc[nb][1] * in0;
        float s10 = acc[nb][2] * in1, s11 = acc[nb][3] * in1;
        float e00 = v0 ? __expf(10.f * s00) : 0.f;
        float e01 = v0 ? __expf(10.f * s01) : 0.f;
        float e10 = v1 ? __expf(10.f * s10) : 0.f;
        float e11 = v1 ? __expf(10.f * s11) : 0.f;
        colSum[2 * nb]     = e00 + e10;
        colSum[2 * nb + 1] = e01 + e11;
        if (n0 == bp) { if (pm0) posAcc += e00; if (pm1) posAcc += e10; }
        if (n1 == bp) { if (pm0) posAcc += e01; if (pm1) posAcc += e11; }
        if (w00) { g_sTop[t0 * BB + n0] = s00; g_sTop[t0 * BB + n1] = s01; }
        if (w01) { g_sTop[t1 * BB + n0] = s00; g_sTop[t1 * BB + n1] = s01; }
        if (w10) { g_sTop[t0 * BB + n0] = s10; g_sTop[t0 * BB + n1] = s11; }
        if (w11) { g_sTop[t1 * BB + n0] = s10; g_sTop[t1 * BB + n1] = s11; }
    }
    // reduce cols across the 8 lanes with same tg
    #pragma unroll
    for (int o = 4; o <= 16; o <<= 1) {
        #pragma unroll
        for (int i = 0; i < 16; i++)
            colSum[i] += __shfl_xor_sync(0xffffffffu, colSum[i], o);
    }
    if (lane < 4) {
        #pragma unroll
        for (int nb = 0; nb < 8; nb++) {
            partQ[wid][nb * 8 + lane * 2]     = colSum[2 * nb];
            partQ[wid][nb * 8 + lane * 2 + 1] = colSum[2 * nb + 1];
        }
    }
    red[tid] = posAcc;
    __syncthreads();

    int blk = bp * NTILE + tileIdx;
    if (tid < BB) {
        float s = 0.f;
        #pragma unroll
        for (int w = 0; w < 8; w++) s += partQ[w][tid];
        g_totQpart[tid * NBLK + blk] = s;   // transposed: [q][blk]
    }
    for (int s = 128; s > 0; s >>= 1) {
        if (tid < s) red[tid] += red[tid + s];
        __syncthreads();
    }
    if (tid == 0) g_posQpart[blk] = red[0];
    if (tid < 2) {
        const float* src = tid ? nb1s : nb0s;
        float s = 0.f;
        for (int pp = 0; pp < TPL; pp++) s += src[pp];
        g_negIpart[blk * 2 + tid] = s;
    }
}

// ---------------- parallel reduction of totQ partials ----------------
__global__ void k_reduce() {
    int q = blockIdx.x, tid = threadIdx.x;  // 256 threads
    __shared__ float red[256];
    float s = 0.f;
    for (int blk = tid; blk < NBLK; blk += 256) s += g_totQpart[q * NBLK + blk];
    red[tid] = s;
    __syncthreads();
    for (int st = 128; st > 0; st >>= 1) {
        if (tid < st) red[tid] += red[tid + st];
        __syncthreads();
    }
    if (tid == 0) g_totQ[q] = red[0];
}

// ---------------- final: assemble the 4 losses ----------------
__global__ void k_final(float* __restrict__ out) {
    __shared__ float totQ[BB], posQ[BB], negI[TT];
    __shared__ float red[256];
    int tid = threadIdx.x;  // 256

    if (tid < BB) {
        totQ[tid] = g_totQ[tid];
        float sp = 0.f;
        for (int ti = 0; ti < NTILE; ti++) sp += g_posQpart[tid * NTILE + ti];
        posQ[tid] = sp;
    }
    if (tid < TT) {
        int b = tid >> 1, j = tid & 1;
        float s = 0.f;
        for (int ti = 0; ti < NTILE; ti++) s += g_negIpart[(b * NTILE + ti) * 2 + j];
        negI[tid] = s;
    }
    __syncthreads();

    float vals[4] = {0.f, 0.f, 0.f, 0.f};
    if (tid < TT) {
        int b = tid >> 1;
        float pos = g_sTop[tid * BB + b];
        float pe = __expf(10.f * pos);
        float ns = 0.f;
        for (int q = 0; q < BB; q++)
            if (q != b) ns += __expf(10.f * g_sTop[tid * BB + q]);
        vals[0] = -(10.f * pos - logf(pe + ns));
        vals[1] = -(10.f * pos - logf(pe + (totQ[b] - posQ[b])));
        float inv0 = 1.f / fmaxf(sqrtf(g_norm2k[2 * b]), 1e-12f);
        float inv1 = 1.f / fmaxf(sqrtf(g_norm2k[2 * b + 1]), 1e-12f);
        float crossn = g_cross[b] * inv0 * inv1;
        float invt = (tid & 1) ? inv1 : inv0;
        float selfn = g_norm2k[tid] * invt * invt;
        float nI = negI[tid];
        vals[2] = -(10.f * selfn  - logf(__expf(10.f * selfn)  + nI))
                + -(10.f * crossn - logf(__expf(10.f * crossn) + nI));
        float posq = g_qs[b * TT + tid];
        float nsq = 0.f;
        for (int t2 = 0; t2 < TT; t2++)
            if ((t2 >> 1) != b) nsq += __expf(10.f * g_qs[b * TT + t2]);
        vals[3] = -(10.f * posq - logf(__expf(10.f * posq) + nsq));
    }
    const float divi[4] = {128.f, 128.f, 256.f, 128.f};
    for (int m = 0; m < 4; m++) {
        red[tid] = vals[m];
        __syncthreads();
        for (int s = 128; s > 0; s >>= 1) {
            if (tid < s) red[tid] += red[tid + s];
            __syncthreads();
        }
        if (tid == 0) out[m] = red[0] / divi[m];
        __syncthreads();
    }
}

// ---------------- launch (k_main 4th for the profile window) ----------------
extern "C" void kernel_launch(void* const* d_in, const int* in_sizes, int n_in,
                              void* d_out, int out_size) {
    const float* vid    = (const float*)d_in[0];
    const float* qf     = (const float*)d_in[1];
    const float* sf     = (const float*)d_in[2];
    const float* iou2d  = (const float*)d_in[3];
    const float* iou2ds = (const float*)d_in[4];
    (void)in_sizes; (void)n_in; (void)out_size;

    cudaFuncSetAttribute(k_main, cudaFuncAttributeMaxDynamicSharedMemorySize, DYN_SMEM);

    k_topkstats<<<BB, 256>>>(iou2ds, vid);
    k_norms    <<<BB + TT, 256>>>(qf, sf);
    k_qs       <<<BB, 256>>>();
    k_main     <<<dim3(NTILE, BB), 256, DYN_SMEM>>>(vid, iou2d);
    k_reduce   <<<BB, 256>>>();
    k_final    <<<1, 256>>>((float*)d_out);
}

// round 12
// speedup vs baseline: 1.1054x; 1.1054x over previous
#include <cuda_runtime.h>
#include <cuda_bf16.h>
#include <math.h>
#include <stdint.h>

// Problem constants (fixed by setup_inputs)
#define BB 64      // batch
#define CC 256     // channels
#define DD 64      // 2D map side
#define TT 128     // total sentences (B * n, n = 2)
#define PP 2080    // triu proposals
#define TPL 128    // proposals per tile (= GEMM M)
#define NTILE 17   // ceil(PP / TPL)
#define NBLK (BB * NTILE)
#define KCH 32     // K floats per chunk
#define NCHUNK (CC / KCH)  // 8
#define VR 40      // smem row stride in bf16 (80B rows; frag loads conflict-free)

// per buffer (bf16 elems): Vh 128*40=5120, Vl 5120, Qh 64*40=2560, Ql 2560
#define BUF_ELEMS 15360
#define DYN_SMEM (2 * BUF_ELEMS * 2)   // 61440 B

// ---------------- scratch (device globals; fully overwritten every launch) ---
__device__ int   g_pk[TT];               // argmax p (triu order) per t
__device__ int   g_pkflat[TT];           // flat r*64+c position
__device__ float g_qn[BB * CC];          // normalized query feats
__device__ __nv_bfloat16 g_qbh[BB * CC]; // bf16 hi of qn
__device__ __nv_bfloat16 g_qbl[BB * CC]; // bf16 lo of qn
__device__ float g_sn[TT * CC];          // normalized sentence feats
__device__ float g_norm2k[TT];           // |v[b', pos_k(t)]|^2
__device__ float g_cross[BB];            // vk0 . vk1 raw dot
__device__ float g_sTop[TT * BB];        // cosine(topk_vf[t], qf_n[b])
__device__ float g_qs[BB * TT];          // qf_n[b] . sf_n[t']
__device__ float g_totQpart[BB * NBLK];  // TRANSPOSED: [q][blk]
__device__ float g_totQ[BB];
__device__ float g_posQpart[NBLK];
__device__ float g_negIpart[NBLK * 2];

// ---------------- mma.sync wrapper (bf16 x bf16 -> f32, m16n8k16) ----------
__device__ __forceinline__ void mma16816(float* d,
                                         uint32_t a0, uint32_t a1,
                                         uint32_t a2, uint32_t a3,
                                         uint32_t b0, uint32_t b1) {
    asm volatile(
        "mma.sync.aligned.m16n8k16.row.col.f32.bf16.bf16.f32 "
        "{%0,%1,%2,%3}, {%4,%5,%6,%7}, {%8,%9}, {%0,%1,%2,%3};"
        : "+f"(d[0]), "+f"(d[1]), "+f"(d[2]), "+f"(d[3])
        : "r"(a0), "r"(a1), "r"(a2), "r"(a3), "r"(b0), "r"(b1));
}

__device__ __forceinline__ uint32_t bf16pair(float lo, float hi) {
    __nv_bfloat162 h2(__float2bfloat16(lo), __float2bfloat16(hi));
    return *(uint32_t*)&h2;
}

// ---------------- topk (K=1) + topk-vector stats, fused per b' ----------------
__global__ void k_topkstats(const float* __restrict__ iou2ds,
                            const float* __restrict__ vid) {
    int b = blockIdx.x, tid = threadIdx.x;  // 256 threads
    __shared__ float bv[256]; __shared__ int bx[256];
    __shared__ int pkf[2];

    for (int j = 0; j < 2; j++) {
        int t = 2 * b + j;
        const float4* row = (const float4*)(iou2ds + (size_t)t * (DD * DD));
        float best = -1e30f; int bf = 0x3fffffff;
        for (int v = tid; v < 1024; v += 256) {
            float4 x = row[v];
            int f0 = v * 4;
            float vals[4] = {x.x, x.y, x.z, x.w};
            #pragma unroll
            for (int e = 0; e < 4; e++) {
                int f = f0 + e, r = f >> 6, c = f & 63;
                if (c >= r && vals[e] > best) { best = vals[e]; bf = f; }
            }
        }
        bv[tid] = best; bx[tid] = bf;
        __syncthreads();
        for (int s = 128; s > 0; s >>= 1) {
            if (tid < s) {
                if (bv[tid + s] > bv[tid] ||
                    (bv[tid + s] == bv[tid] && bx[tid + s] < bx[tid])) {
                    bv[tid] = bv[tid + s]; bx[tid] = bx[tid + s];
                }
            }
            __syncthreads();
        }
        if (tid == 0) {
            int f = bx[0], r = f >> 6, c = f & 63;
            g_pk[t] = r * 64 - (r * (r - 1)) / 2 + (c - r);
            g_pkflat[t] = f;
            pkf[j] = f;
        }
        __syncthreads();
    }

    int pk0 = pkf[0], pk1 = pkf[1];
    const float* vb = vid + (size_t)b * CC * (DD * DD);
    float v0 = vb[(size_t)tid * (DD * DD) + pk0];
    float v1 = vb[(size_t)tid * (DD * DD) + pk1];
    float a = v0 * v0, d2 = v1 * v1, x = v0 * v1;
    for (int o = 16; o > 0; o >>= 1) {
        a  += __shfl_xor_sync(0xffffffffu, a, o);
        d2 += __shfl_xor_sync(0xffffffffu, d2, o);
        x  += __shfl_xor_sync(0xffffffffu, x, o);
    }
    __shared__ float sa[8], sd[8], sx[8];
    if ((tid & 31) == 0) { sa[tid >> 5] = a; sd[tid >> 5] = d2; sx[tid >> 5] = x; }
    __syncthreads();
    if (tid == 0) {
        float ta = 0, td = 0, tc = 0;
        for (int w = 0; w < 8; w++) { ta += sa[w]; td += sd[w]; tc += sx[w]; }
        g_norm2k[2 * b] = ta; g_norm2k[2 * b + 1] = td; g_cross[b] = tc;
    }
}

// ---------------- row normalization (fused q + s) ----------------
__device__ __forceinline__ float blk_sumsq(float v) {
    float s = v * v;
    for (int o = 16; o > 0; o >>= 1) s += __shfl_xor_sync(0xffffffffu, s, o);
    __shared__ float ws[8];
    int tid = threadIdx.x;
    if ((tid & 31) == 0) ws[tid >> 5] = s;
    __syncthreads();
    return ws[0] + ws[1] + ws[2] + ws[3] + ws[4] + ws[5] + ws[6] + ws[7];
}

__global__ void k_norms(const float* __restrict__ q, const float* __restrict__ s) {
    int row = blockIdx.x, tid = threadIdx.x;
    if (row < BB) {
        float v = q[row * CC + tid];
        float inv = 1.0f / fmaxf(sqrtf(blk_sumsq(v)), 1e-12f);
        float nv = v * inv;
        g_qn[row * CC + tid] = nv;
        __nv_bfloat16 h = __float2bfloat16(nv);
        g_qbh[row * CC + tid] = h;
        g_qbl[row * CC + tid] = __float2bfloat16(nv - __bfloat162float(h));
    } else {
        int r = row - BB;
        float v = s[r * CC + tid];
        float inv = 1.0f / fmaxf(sqrtf(blk_sumsq(v)), 1e-12f);
        g_sn[r * CC + tid] = v * inv;
    }
}

// ---------------- qf_n @ sf_n^T (tiny) ----------------
__global__ void k_qs() {
    int b = blockIdx.x, tid = threadIdx.x;
    __shared__ float qsh[CC];
    qsh[tid] = g_qn[b * CC + tid];
    __syncthreads();
    int w = tid >> 5, lane = tid & 31;
    for (int t2 = w; t2 < TT; t2 += 8) {
        float a = 0.f;
        for (int c = lane; c < CC; c += 32) a += qsh[c] * g_sn[t2 * CC + c];
        for (int o = 16; o > 0; o >>= 1) a += __shfl_xor_sync(0xffffffffu, a, o);
        if (lane == 0) g_qs[b * TT + t2] = a;
    }
}

// ---------------- main fused pass: pipelined mma.sync bf16 hi/lo GEMM -------
// grid (NTILE, BB), 256 threads (8 warps). Double-buffered smem tiles,
// register-prefetched gather overlapping the MMA. One barrier per chunk.
// (R10 version — no reg cap: prefetch MLP needs the registers.)
__global__ void __launch_bounds__(256) k_main(const float* __restrict__ vid,
                                              const float* __restrict__ iou2d) {
    extern __shared__ __align__(16) char dyn[];
    __nv_bfloat16* sbase = (__nv_bfloat16*)dyn;

    __shared__ float vk0s[CC], vk1s[CC];
    __shared__ int   posArr[TPL];
    __shared__ float ioul[TPL], invnS[TPL];
    __shared__ float statA[256], stat0[256], stat1[256];
    __shared__ float partQ[8][64];
    __shared__ float red[256];
    __shared__ float nb0s[TPL], nb1s[TPL];

    int tileIdx = blockIdx.x, bp = blockIdx.y;
    int p0 = tileIdx * TPL;
    int tid = threadIdx.x, wid = tid >> 5, lane = tid & 31;

    const float* vb = vid + (size_t)bp * CC * (DD * DD);
    int t0 = 2 * bp, t1 = t0 + 1;
    int pkI0 = g_pk[t0], pkI1 = g_pk[t1];
    int pf0 = g_pkflat[t0], pf1 = g_pkflat[t1];
    vk0s[tid] = vb[(size_t)tid * (DD * DD) + pf0];
    vk1s[tid] = vb[(size_t)tid * (DD * DD) + pf1];

    if (tid < TPL) {
        int pg = p0 + tid;
        int pc = pg < PP ? pg : PP - 1;  // clamp; masked in epilogue
        int r = (int)(64.5f - sqrtf(64.5f * 64.5f - 2.0f * (float)pc));
        while (r > 0  && r * 64 - (r * (r - 1)) / 2 > pc) r--;
        while (r < 63 && (r + 1) * 64 - ((r + 1) * r) / 2 <= pc) r++;
        int start = r * 64 - (r * (r - 1)) / 2;
        int pos = r * 64 + (r + (pc - start));
        posArr[tid] = pos;
        ioul[tid] = iou2d[bp * (DD * DD) + pos];
    }
    __syncthreads();

    int p = tid & 127, kh = tid >> 7;       // gather role: (proposal, k-half of 16)
    const float* gp = vb + posArr[p];
    float an = 0.f, a0 = 0.f, a1 = 0.f;

    float acc[8][4] = {};                   // 8 n-blocks x 4 f32
    int g = lane >> 2, tg = lane & 3;       // fragment group ids

    // prefetch chunk 0
    float pf[16];
    #pragma unroll
    for (int j = 0; j < 16; j++)
        pf[j] = gp[(size_t)(kh * 16 + j) * (DD * DD)];

    for (int c = 0; c < NCHUNK; c++) {
        int kb = c * KCH;
        int buf = c & 1;
        __nv_bfloat16* Vh = sbase + buf * BUF_ELEMS;
        __nv_bfloat16* Vl = Vh + 5120;
        __nv_bfloat16* Qh = Vh + 10240;
        __nv_bfloat16* Ql = Vh + 12800;

        // ---- convert prefetched V -> smem (hi/lo), stats ride along ----
        #pragma unroll
        for (int j = 0; j < 16; j += 4) {
            int k = kb + kh * 16 + j;
            float v0 = pf[j], v1 = pf[j + 1], v2 = pf[j + 2], v3 = pf[j + 3];
            an += v0 * v0 + v1 * v1 + v2 * v2 + v3 * v3;
            a0 += v0 * vk0s[k] + v1 * vk0s[k + 1] + v2 * vk0s[k + 2] + v3 * vk0s[k + 3];
            a1 += v0 * vk1s[k] + v1 * vk1s[k + 1] + v2 * vk1s[k + 2] + v3 * vk1s[k + 3];
            __nv_bfloat16 h0 = __float2bfloat16(v0), h1 = __float2bfloat16(v1);
            __nv_bfloat16 h2 = __float2bfloat16(v2), h3 = __float2bfloat16(v3);
            uint2 hb, lb;
            { __nv_bfloat162 t01(h0, h1), t23(h2, h3);
              hb.x = *(uint32_t*)&t01; hb.y = *(uint32_t*)&t23; }
            lb.x = bf16pair(v0 - __bfloat162float(h0), v1 - __bfloat162float(h1));
            lb.y = bf16pair(v2 - __bfloat162float(h2), v3 - __bfloat162float(h3));
            int so = p * VR + kh * 16 + j;
            *(uint2*)&Vh[so] = hb;
            *(uint2*)&Vl[so] = lb;
        }
        // ---- Q tiles: 64 q x 16 u32-pairs each, coalesced (L1-hot) ----
        #pragma unroll
        for (int i = 0; i < 4; i++) {
            int idx = tid + i * 256;          // 0..1023
            int q = idx >> 4, kp = idx & 15;
            *(uint32_t*)&Qh[q * VR + kp * 2] = *(const uint32_t*)&g_qbh[q * CC + kb + kp * 2];
            *(uint32_t*)&Ql[q * VR + kp * 2] = *(const uint32_t*)&g_qbl[q * CC + kb + kp * 2];
        }
        __syncthreads();

        // ---- issue next chunk's gather (overlaps MMA below) ----
        if (c + 1 < NCHUNK) {
            int kn = (c + 1) * KCH + kh * 16;
            #pragma unroll
            for (int j = 0; j < 16; j++)
                pf[j] = gp[(size_t)(kn + j) * (DD * DD)];
        }

        // ---- MMA: warp w rows w*16.., all 64 cols, 2 k-steps ----
        int rA = wid * 16 + g;
        #pragma unroll
        for (int ks = 0; ks < 2; ks++) {
            int k0 = ks * 16;
            const __nv_bfloat16* ah = &Vh[rA * VR + k0 + tg * 2];
            const __nv_bfloat16* al = &Vl[rA * VR + k0 + tg * 2];
            uint32_t ah0 = *(const uint32_t*)(ah);
            uint32_t ah1 = *(const uint32_t*)(ah + 8 * VR);
            uint32_t ah2 = *(const uint32_t*)(ah + 8);
            uint32_t ah3 = *(const uint32_t*)(ah + 8 * VR + 8);
            uint32_t al0 = *(const uint32_t*)(al);
            uint32_t al1 = *(const uint32_t*)(al + 8 * VR);
            uint32_t al2 = *(const uint32_t*)(al + 8);
            uint32_t al3 = *(const uint32_t*)(al + 8 * VR + 8);
            #pragma unroll
            for (int nb = 0; nb < 8; nb++) {
                const __nv_bfloat16* bh = &Qh[(nb * 8 + g) * VR + k0 + tg * 2];
                const __nv_bfloat16* bl = &Ql[(nb * 8 + g) * VR + k0 + tg * 2];
                uint32_t bh0 = *(const uint32_t*)(bh);
                uint32_t bh1 = *(const uint32_t*)(bh + 8);
                uint32_t bl0 = *(const uint32_t*)(bl);
                uint32_t bl1 = *(const uint32_t*)(bl + 8);
                mma16816(acc[nb], ah0, ah1, ah2, ah3, bh0, bh1);
                mma16816(acc[nb], ah0, ah1, ah2, ah3, bl0, bl1);
                mma16816(acc[nb], al0, al1, al2, al3, bh0, bh1);
            }
        }
        // no trailing barrier: double-buffered; next write targets other buffer.
    }

    // ---- stats combine (p owned by 2 threads: kh halves) ----
    statA[tid] = an; stat0[tid] = a0; stat1[tid] = a1;
    __syncthreads();
    if (tid < TPL) {
        float n2 = statA[tid] + statA[tid + 128];
        float inv = 1.0f / fmaxf(sqrtf(n2), 1e-12f);
        invnS[tid] = inv;
        float i0 = stat0[tid] + stat0[tid + 128];
        float i1 = stat1[tid] + stat1[tid + 128];
        bool negm = (p0 + tid < PP) && (ioul[tid] < 0.5f);
        float invk0 = 1.0f / fmaxf(sqrtf(g_norm2k[t0]), 1e-12f);
        float invk1 = 1.0f / fmaxf(sqrtf(g_norm2k[t1]), 1e-12f);
        nb0s[tid] = negm ? __expf(10.0f * i0 * inv * invk0) : 0.f;
        nb1s[tid] = negm ? __expf(10.0f * i1 * inv * invk1) : 0.f;
    }
    __syncthreads();

    // ---- epilogue: scores -> exp -> column partials ----
    int rl0 = wid * 16 + g, rl1 = rl0 + 8;
    int pg0 = p0 + rl0, pg1 = p0 + rl1;
    bool v0 = pg0 < PP, v1 = pg1 < PP;
    float in0 = invnS[rl0], in1 = invnS[rl1];
    bool pm0 = v0 && (ioul[rl0] > 0.5f), pm1 = v1 && (ioul[rl1] > 0.5f);
    bool w00 = (pg0 == pkI0), w01 = (pg0 == pkI1);
    bool w10 = (pg1 == pkI0), w11 = (pg1 == pkI1);

    float colSum[16];
    float posAcc = 0.f;
    #pragma unroll
    for (int nb = 0; nb < 8; nb++) {
        int n0 = nb * 8 + tg * 2, n1 = n0 + 1;
        float s00 = acc[nb][0] * in0, s01 = acc[nb][1] * in0;
        float s10 = acc[nb][2] * in1, s11 = acc[nb][3] * in1;
        float e00 = v0 ? __expf(10.f * s00) : 0.f;
        float e01 = v0 ? __expf(10.f * s01) : 0.f;
        float e10 = v1 ? __expf(10.f * s10) : 0.f;
        float e11 = v1 ? __expf(10.f * s11) : 0.f;
        colSum[2 * nb]     = e00 + e10;
        colSum[2 * nb + 1] = e01 + e11;
        if (n0 == bp) { if (pm0) posAcc += e00; if (pm1) posAcc += e10; }
        if (n1 == bp) { if (pm0) posAcc += e01; if (pm1) posAcc += e11; }
        if (w00) { g_sTop[t0 * BB + n0] = s00; g_sTop[t0 * BB + n1] = s01; }
        if (w01) { g_sTop[t1 * BB + n0] = s00; g_sTop[t1 * BB + n1] = s01; }
        if (w10) { g_sTop[t0 * BB + n0] = s10; g_sTop[t0 * BB + n1] = s11; }
        if (w11) { g_sTop[t1 * BB + n0] = s10; g_sTop[t1 * BB + n1] = s11; }
    }
    // reduce cols across the 8 lanes with same tg
    #pragma unroll
    for (int o = 4; o <= 16; o <<= 1) {
        #pragma unroll
        for (int i = 0; i < 16; i++)
            colSum[i] += __shfl_xor_sync(0xffffffffu, colSum[i], o);
    }
    if (lane < 4) {
        #pragma unroll
        for (int nb = 0; nb < 8; nb++) {
            partQ[wid][nb * 8 + lane * 2]     = colSum[2 * nb];
            partQ[wid][nb * 8 + lane * 2 + 1] = colSum[2 * nb + 1];
        }
    }
    red[tid] = posAcc;
    __syncthreads();

    int blk = bp * NTILE + tileIdx;
    if (tid < BB) {
        float s = 0.f;
        #pragma unroll
        for (int w = 0; w < 8; w++) s += partQ[w][tid];
        g_totQpart[tid * NBLK + blk] = s;   // transposed: [q][blk]
    }
    for (int s = 128; s > 0; s >>= 1) {
        if (tid < s) red[tid] += red[tid + s];
        __syncthreads();
    }
    if (tid == 0) g_posQpart[blk] = red[0];
    if (tid < 2) {
        const float* src = tid ? nb1s : nb0s;
        float s = 0.f;
        for (int pp = 0; pp < TPL; pp++) s += src[pp];
        g_negIpart[blk * 2 + tid] = s;
    }
}

// ---------------- parallel reduction of totQ partials ----------------
__global__ void k_reduce() {
    int q = blockIdx.x, tid = threadIdx.x;  // 256 threads
    __shared__ float red[256];
    float s = 0.f;
    for (int blk = tid; blk < NBLK; blk += 256) s += g_totQpart[q * NBLK + blk];
    red[tid] = s;
    __syncthreads();
    for (int st = 128; st > 0; st >>= 1) {
        if (tid < st) red[tid] += red[tid + st];
        __syncthreads();
    }
    if (tid == 0) g_totQ[q] = red[0];
}

// ---------------- final: assemble the 4 losses ----------------
__global__ void k_final(float* __restrict__ out) {
    __shared__ float totQ[BB], posQ[BB], negI[TT];
    __shared__ float red[256];
    int tid = threadIdx.x;  // 256

    if (tid < BB) {
        totQ[tid] = g_totQ[tid];
        float sp = 0.f;
        for (int ti = 0; ti < NTILE; ti++) sp += g_posQpart[tid * NTILE + ti];
        posQ[tid] = sp;
    }
    if (tid < TT) {
        int b = tid >> 1, j = tid & 1;
        float s = 0.f;
        for (int ti = 0; ti < NTILE; ti++) s += g_negIpart[(b * NTILE + ti) * 2 + j];
        negI[tid] = s;
    }
    __syncthreads();

    float vals[4] = {0.f, 0.f, 0.f, 0.f};
    if (tid < TT) {
        int b = tid >> 1;
        float pos = g_sTop[tid * BB + b];
        float pe = __expf(10.f * pos);
        float ns = 0.f;
        for (int q = 0; q < BB; q++)
            if (q != b) ns += __expf(10.f * g_sTop[tid * BB + q]);
        vals[0] = -(10.f * pos - logf(pe + ns));
        vals[1] = -(10.f * pos - logf(pe + (totQ[b] - posQ[b])));
        float inv0 = 1.f / fmaxf(sqrtf(g_norm2k[2 * b]), 1e-12f);
        float inv1 = 1.f / fmaxf(sqrtf(g_norm2k[2 * b + 1]), 1e-12f);
        float crossn = g_cross[b] * inv0 * inv1;
        float invt = (tid & 1) ? inv1 : inv0;
        float selfn = g_norm2k[tid] * invt * invt;
        float nI = negI[tid];
        vals[2] = -(10.f * selfn  - logf(__expf(10.f * selfn)  + nI))
                + -(10.f * crossn - logf(__expf(10.f * crossn) + nI));
        float posq = g_qs[b * TT + tid];
        float nsq = 0.f;
        for (int t2 = 0; t2 < TT; t2++)
            if ((t2 >> 1) != b) nsq += __expf(10.f * g_qs[b * TT + t2]);
        vals[3] = -(10.f * posq - logf(__expf(10.f * posq) + nsq));
    }
    const float divi[4] = {128.f, 128.f, 256.f, 128.f};
    for (int m = 0; m < 4; m++) {
        red[tid] = vals[m];
        __syncthreads();
        for (int s = 128; s > 0; s >>= 1) {
            if (tid < s) red[tid] += red[tid + s];
            __syncthreads();
        }
        if (tid == 0) out[m] = red[0] / divi[m];
        __syncthreads();
    }
}

// ---------------- launch (k_main 4th for the profile window) ----------------
extern "C" void kernel_launch(void* const* d_in, const int* in_sizes, int n_in,
                              void* d_out, int out_size) {
    const float* vid    = (const float*)d_in[0];
    const float* qf     = (const float*)d_in[1];
    const float* sf     = (const float*)d_in[2];
    const float* iou2d  = (const float*)d_in[3];
    const float* iou2ds = (const float*)d_in[4];
    (void)in_sizes; (void)n_in; (void)out_size;

    cudaFuncSetAttribute(k_main, cudaFuncAttributeMaxDynamicSharedMemorySize, DYN_SMEM);

    k_topkstats<<<BB, 256>>>(iou2ds, vid);
    k_norms    <<<BB + TT, 256>>>(qf, sf);
    k_qs       <<<BB, 256>>>();
    k_main     <<<dim3(NTILE, BB), 256, DYN_SMEM>>>(vid, iou2d);
    k_reduce   <<<BB, 256>>>();
    k_final    <<<1, 256>>>((float*)d_out);
}

// round 13
// speedup vs baseline: 1.1624x; 1.0515x over previous
#include <cuda_runtime.h>
#include <cuda_bf16.h>
#include <math.h>
#include <stdint.h>

// Problem constants (fixed by setup_inputs)
#define BB 64      // batch
#define CC 256     // channels
#define DD 64      // 2D map side
#define TT 128     // total sentences (B * n, n = 2)
#define PP 2080    // triu proposals
#define TPL 128    // proposals per tile (= GEMM M)
#define NTILE 17   // ceil(PP / TPL)
#define NBLK (BB * NTILE)
#define KCH 32     // K floats per chunk
#define NCHUNK (CC / KCH)  // 8
#define VR 40      // smem row stride in bf16 (80B rows; conflict-free ldmatrix)

// per buffer (bf16 elems): Vh 128*40=5120, Vl 5120, Qh 64*40=2560, Ql 2560
#define BUF_ELEMS 15360
#define DYN_SMEM (2 * BUF_ELEMS * 2)   // 61440 B

// ---------------- scratch (device globals; fully overwritten every launch) ---
__device__ int   g_pk[TT];               // argmax p (triu order) per t
__device__ int   g_pkflat[TT];           // flat r*64+c position
__device__ float g_qn[BB * CC];          // normalized query feats
__device__ __nv_bfloat16 g_qbh[BB * CC]; // bf16 hi of qn
__device__ __nv_bfloat16 g_qbl[BB * CC]; // bf16 lo of qn
__device__ float g_sn[TT * CC];          // normalized sentence feats
__device__ float g_norm2k[TT];           // |v[b', pos_k(t)]|^2
__device__ float g_cross[BB];            // vk0 . vk1 raw dot
__device__ float g_sTop[TT * BB];        // cosine(topk_vf[t], qf_n[b])
__device__ float g_qs[BB * TT];          // qf_n[b] . sf_n[t']
__device__ float g_totQpart[BB * NBLK];  // TRANSPOSED: [q][blk]
__device__ float g_totQ[BB];
__device__ float g_posQpart[NBLK];
__device__ float g_negIpart[NBLK * 2];

// ---------------- mma.sync + ldmatrix wrappers ----------------
__device__ __forceinline__ void mma16816(float* d,
                                         uint32_t a0, uint32_t a1,
                                         uint32_t a2, uint32_t a3,
                                         uint32_t b0, uint32_t b1) {
    asm volatile(
        "mma.sync.aligned.m16n8k16.row.col.f32.bf16.bf16.f32 "
        "{%0,%1,%2,%3}, {%4,%5,%6,%7}, {%8,%9}, {%0,%1,%2,%3};"
        : "+f"(d[0]), "+f"(d[1]), "+f"(d[2]), "+f"(d[3])
        : "r"(a0), "r"(a1), "r"(a2), "r"(a3), "r"(b0), "r"(b1));
}

__device__ __forceinline__ void ldsm_x4(uint32_t& r0, uint32_t& r1,
                                        uint32_t& r2, uint32_t& r3, uint32_t a) {
    asm volatile("ldmatrix.sync.aligned.m8n8.x4.shared.b16 {%0,%1,%2,%3}, [%4];"
                 : "=r"(r0), "=r"(r1), "=r"(r2), "=r"(r3) : "r"(a));
}

__device__ __forceinline__ uint32_t bf16pair(float lo, float hi) {
    __nv_bfloat162 h2(__float2bfloat16(lo), __float2bfloat16(hi));
    return *(uint32_t*)&h2;
}

// ---------------- topk (K=1) + topk-vector stats, fused per b' ----------------
__global__ void k_topkstats(const float* __restrict__ iou2ds,
                            const float* __restrict__ vid) {
    int b = blockIdx.x, tid = threadIdx.x;  // 256 threads
    __shared__ float bv[256]; __shared__ int bx[256];
    __shared__ int pkf[2];

    for (int j = 0; j < 2; j++) {
        int t = 2 * b + j;
        const float4* row = (const float4*)(iou2ds + (size_t)t * (DD * DD));
        float best = -1e30f; int bf = 0x3fffffff;
        for (int v = tid; v < 1024; v += 256) {
            float4 x = row[v];
            int f0 = v * 4;
            float vals[4] = {x.x, x.y, x.z, x.w};
            #pragma unroll
            for (int e = 0; e < 4; e++) {
                int f = f0 + e, r = f >> 6, c = f & 63;
                if (c >= r && vals[e] > best) { best = vals[e]; bf = f; }
            }
        }
        bv[tid] = best; bx[tid] = bf;
        __syncthreads();
        for (int s = 128; s > 0; s >>= 1) {
            if (tid < s) {
                if (bv[tid + s] > bv[tid] ||
                    (bv[tid + s] == bv[tid] && bx[tid + s] < bx[tid])) {
                    bv[tid] = bv[tid + s]; bx[tid] = bx[tid + s];
                }
            }
            __syncthreads();
        }
        if (tid == 0) {
            int f = bx[0], r = f >> 6, c = f & 63;
            g_pk[t] = r * 64 - (r * (r - 1)) / 2 + (c - r);
            g_pkflat[t] = f;
            pkf[j] = f;
        }
        __syncthreads();
    }

    int pk0 = pkf[0], pk1 = pkf[1];
    const float* vb = vid + (size_t)b * CC * (DD * DD);
    float v0 = vb[(size_t)tid * (DD * DD) + pk0];
    float v1 = vb[(size_t)tid * (DD * DD) + pk1];
    float a = v0 * v0, d2 = v1 * v1, x = v0 * v1;
    for (int o = 16; o > 0; o >>= 1) {
        a  += __shfl_xor_sync(0xffffffffu, a, o);
        d2 += __shfl_xor_sync(0xffffffffu, d2, o);
        x  += __shfl_xor_sync(0xffffffffu, x, o);
    }
    __shared__ float sa[8], sd[8], sx[8];
    if ((tid & 31) == 0) { sa[tid >> 5] = a; sd[tid >> 5] = d2; sx[tid >> 5] = x; }
    __syncthreads();
    if (tid == 0) {
        float ta = 0, td = 0, tc = 0;
        for (int w = 0; w < 8; w++) { ta += sa[w]; td += sd[w]; tc += sx[w]; }
        g_norm2k[2 * b] = ta; g_norm2k[2 * b + 1] = td; g_cross[b] = tc;
    }
}

// ---------------- row normalization (fused q + s) ----------------
__device__ __forceinline__ float blk_sumsq(float v) {
    float s = v * v;
    for (int o = 16; o > 0; o >>= 1) s += __shfl_xor_sync(0xffffffffu, s, o);
    __shared__ float ws[8];
    int tid = threadIdx.x;
    if ((tid & 31) == 0) ws[tid >> 5] = s;
    __syncthreads();
    return ws[0] + ws[1] + ws[2] + ws[3] + ws[4] + ws[5] + ws[6] + ws[7];
}

__global__ void k_norms(const float* __restrict__ q, const float* __restrict__ s) {
    int row = blockIdx.x, tid = threadIdx.x;
    if (row < BB) {
        float v = q[row * CC + tid];
        float inv = 1.0f / fmaxf(sqrtf(blk_sumsq(v)), 1e-12f);
        float nv = v * inv;
        g_qn[row * CC + tid] = nv;
        __nv_bfloat16 h = __float2bfloat16(nv);
        g_qbh[row * CC + tid] = h;
        g_qbl[row * CC + tid] = __float2bfloat16(nv - __bfloat162float(h));
    } else {
        int r = row - BB;
        float v = s[r * CC + tid];
        float inv = 1.0f / fmaxf(sqrtf(blk_sumsq(v)), 1e-12f);
        g_sn[r * CC + tid] = v * inv;
    }
}

// ---------------- qf_n @ sf_n^T (tiny) ----------------
__global__ void k_qs() {
    int b = blockIdx.x, tid = threadIdx.x;
    __shared__ float qsh[CC];
    qsh[tid] = g_qn[b * CC + tid];
    __syncthreads();
    int w = tid >> 5, lane = tid & 31;
    for (int t2 = w; t2 < TT; t2 += 8) {
        float a = 0.f;
        for (int c = lane; c < CC; c += 32) a += qsh[c] * g_sn[t2 * CC + c];
        for (int o = 16; o > 0; o >>= 1) a += __shfl_xor_sync(0xffffffffu, a, o);
        if (lane == 0) g_qs[b * TT + t2] = a;
    }
}

// ---------------- main fused pass: pipelined mma.sync + ldmatrix ------------
// grid (NTILE, BB), 256 threads (8 warps). Double-buffered smem tiles,
// register-prefetched gather overlapping the MMA. One barrier per chunk.
// NO register cap (prefetch MLP needs the registers); ldmatrix fragment loads.
__global__ void __launch_bounds__(256) k_main(const float* __restrict__ vid,
                                              const float* __restrict__ iou2d) {
    extern __shared__ __align__(16) char dyn[];
    __nv_bfloat16* sbase = (__nv_bfloat16*)dyn;
    uint32_t sAddr = (uint32_t)__cvta_generic_to_shared(sbase);

    __shared__ float vk0s[CC], vk1s[CC];
    __shared__ int   posArr[TPL];
    __shared__ float ioul[TPL], invnS[TPL];
    __shared__ float statA[256], stat0[256], stat1[256];
    __shared__ float partQ[8][64];
    __shared__ float red[256];
    __shared__ float nb0s[TPL], nb1s[TPL];

    int tileIdx = blockIdx.x, bp = blockIdx.y;
    int p0 = tileIdx * TPL;
    int tid = threadIdx.x, wid = tid >> 5, lane = tid & 31;

    const float* vb = vid + (size_t)bp * CC * (DD * DD);
    int t0 = 2 * bp, t1 = t0 + 1;
    int pkI0 = g_pk[t0], pkI1 = g_pk[t1];
    int pf0 = g_pkflat[t0], pf1 = g_pkflat[t1];
    vk0s[tid] = vb[(size_t)tid * (DD * DD) + pf0];
    vk1s[tid] = vb[(size_t)tid * (DD * DD) + pf1];

    if (tid < TPL) {
        int pg = p0 + tid;
        int pc = pg < PP ? pg : PP - 1;  // clamp; masked in epilogue
        int r = (int)(64.5f - sqrtf(64.5f * 64.5f - 2.0f * (float)pc));
        while (r > 0  && r * 64 - (r * (r - 1)) / 2 > pc) r--;
        while (r < 63 && (r + 1) * 64 - ((r + 1) * r) / 2 <= pc) r++;
        int start = r * 64 - (r * (r - 1)) / 2;
        int pos = r * 64 + (r + (pc - start));
        posArr[tid] = pos;
        ioul[tid] = iou2d[bp * (DD * DD) + pos];
    }
    __syncthreads();

    int p = tid & 127, kh = tid >> 7;       // gather role: (proposal, k-half of 16)
    const float* gp = vb + posArr[p];
    float an = 0.f, a0 = 0.f, a1 = 0.f;

    float acc[8][4] = {};                   // 8 n-blocks x 4 f32
    int g = lane >> 2, tg = lane & 3;       // fragment group ids

    // ldmatrix per-lane address offsets (bytes)
    uint32_t aoffA = ((uint32_t)((wid * 16 + (lane & 15)) * VR) +
                      ((lane >> 4) << 3)) * 2u;
    uint32_t boffB = ((uint32_t)(((lane & 7) + ((lane & 16) ? 8 : 0)) * VR) +
                      ((lane & 8) ? 8 : 0)) * 2u;

    // prefetch chunk 0
    float pf[16];
    #pragma unroll
    for (int j = 0; j < 16; j++)
        pf[j] = gp[(size_t)(kh * 16 + j) * (DD * DD)];

    for (int c = 0; c < NCHUNK; c++) {
        int kb = c * KCH;
        int buf = c & 1;
        __nv_bfloat16* Vh = sbase + buf * BUF_ELEMS;
        __nv_bfloat16* Vl = Vh + 5120;
        __nv_bfloat16* Qh = Vh + 10240;
        __nv_bfloat16* Ql = Vh + 12800;
        uint32_t sV = sAddr + (uint32_t)buf * (BUF_ELEMS * 2u);

        // ---- convert prefetched V -> smem (hi/lo), stats ride along ----
        #pragma unroll
        for (int j = 0; j < 16; j += 4) {
            int k = kb + kh * 16 + j;
            float v0 = pf[j], v1 = pf[j + 1], v2 = pf[j + 2], v3 = pf[j + 3];
            an += v0 * v0 + v1 * v1 + v2 * v2 + v3 * v3;
            a0 += v0 * vk0s[k] + v1 * vk0s[k + 1] + v2 * vk0s[k + 2] + v3 * vk0s[k + 3];
            a1 += v0 * vk1s[k] + v1 * vk1s[k + 1] + v2 * vk1s[k + 2] + v3 * vk1s[k + 3];
            __nv_bfloat16 h0 = __float2bfloat16(v0), h1 = __float2bfloat16(v1);
            __nv_bfloat16 h2 = __float2bfloat16(v2), h3 = __float2bfloat16(v3);
            uint2 hb, lb;
            { __nv_bfloat162 t01(h0, h1), t23(h2, h3);
              hb.x = *(uint32_t*)&t01; hb.y = *(uint32_t*)&t23; }
            lb.x = bf16pair(v0 - __bfloat162float(h0), v1 - __bfloat162float(h1));
            lb.y = bf16pair(v2 - __bfloat162float(h2), v3 - __bfloat162float(h3));
            int so = p * VR + kh * 16 + j;
            *(uint2*)&Vh[so] = hb;
            *(uint2*)&Vl[so] = lb;
        }
        // ---- Q tiles: 64 q x 16 u32-pairs each, coalesced (L1-hot) ----
        #pragma unroll
        for (int i = 0; i < 4; i++) {
            int idx = tid + i * 256;          // 0..1023
            int q = idx >> 4, kp = idx & 15;
            *(uint32_t*)&Qh[q * VR + kp * 2] = *(const uint32_t*)&g_qbh[q * CC + kb + kp * 2];
            *(uint32_t*)&Ql[q * VR + kp * 2] = *(const uint32_t*)&g_qbl[q * CC + kb + kp * 2];
        }
        __syncthreads();

        // ---- issue next chunk's gather (overlaps MMA below) ----
        if (c + 1 < NCHUNK) {
            int kn = (c + 1) * KCH + kh * 16;
            #pragma unroll
            for (int j = 0; j < 16; j++)
                pf[j] = gp[(size_t)(kn + j) * (DD * DD)];
        }

        // ---- MMA via ldmatrix: warp w rows w*16.., all 64 cols, 2 k-steps --
        #pragma unroll
        for (int ks = 0; ks < 2; ks++) {
            uint32_t kadd = (uint32_t)(ks * 32);   // 16 bf16 * 2B
            uint32_t ah0, ah1, ah2, ah3, al0, al1, al2, al3;
            ldsm_x4(ah0, ah1, ah2, ah3, sV + aoffA + kadd);
            ldsm_x4(al0, al1, al2, al3, sV + aoffA + kadd + 10240u);  // Vl
            #pragma unroll
            for (int j = 0; j < 4; j++) {
                uint32_t bq = sV + 20480u + boffB + (uint32_t)(j * (16 * VR * 2)) + kadd;
                uint32_t bh0, bh1, bh2, bh3, bl0, bl1, bl2, bl3;
                ldsm_x4(bh0, bh1, bh2, bh3, bq);            // Qh
                ldsm_x4(bl0, bl1, bl2, bl3, bq + 5120u);    // Ql
                mma16816(acc[2 * j],     ah0, ah1, ah2, ah3, bh0, bh1);
                mma16816(acc[2 * j],     ah0, ah1, ah2, ah3, bl0, bl1);
                mma16816(acc[2 * j],     al0, al1, al2, al3, bh0, bh1);
                mma16816(acc[2 * j + 1], ah0, ah1, ah2, ah3, bh2, bh3);
                mma16816(acc[2 * j + 1], ah0, ah1, ah2, ah3, bl2, bl3);
                mma16816(acc[2 * j + 1], al0, al1, al2, al3, bh2, bh3);
            }
        }
        // no trailing barrier: double-buffered; next write targets other buffer.
    }

    // ---- stats combine (p owned by 2 threads: kh halves) ----
    statA[tid] = an; stat0[tid] = a0; stat1[tid] = a1;
    __syncthreads();
    if (tid < TPL) {
        float n2 = statA[tid] + statA[tid + 128];
        float inv = 1.0f / fmaxf(sqrtf(n2), 1e-12f);
        invnS[tid] = inv;
        float i0 = stat0[tid] + stat0[tid + 128];
        float i1 = stat1[tid] + stat1[tid + 128];
        bool negm = (p0 + tid < PP) && (ioul[tid] < 0.5f);
        float invk0 = 1.0f / fmaxf(sqrtf(g_norm2k[t0]), 1e-12f);
        float invk1 = 1.0f / fmaxf(sqrtf(g_norm2k[t1]), 1e-12f);
        nb0s[tid] = negm ? __expf(10.0f * i0 * inv * invk0) : 0.f;
        nb1s[tid] = negm ? __expf(10.0f * i1 * inv * invk1) : 0.f;
    }
    __syncthreads();

    // ---- epilogue: scores -> exp -> column partials ----
    int rl0 = wid * 16 + g, rl1 = rl0 + 8;
    int pg0 = p0 + rl0, pg1 = p0 + rl1;
    bool v0 = pg0 < PP, v1 = pg1 < PP;
    float in0 = invnS[rl0], in1 = invnS[rl1];
    bool pm0 = v0 && (ioul[rl0] > 0.5f), pm1 = v1 && (ioul[rl1] > 0.5f);
    bool w00 = (pg0 == pkI0), w01 = (pg0 == pkI1);
    bool w10 = (pg1 == pkI0), w11 = (pg1 == pkI1);

    float colSum[16];
    float posAcc = 0.f;
    #pragma unroll
    for (int nb = 0; nb < 8; nb++) {
        int n0 = nb * 8 + tg * 2, n1 = n0 + 1;
        float s00 = acc[nb][0] * in0, s01 = acc[nb][1] * in0;
        float s10 = acc[nb][2] * in1, s11 = acc[nb][3] * in1;
        float e00 = v0 ? __expf(10.f * s00) : 0.f;
        float e01 = v0 ? __expf(10.f * s01) : 0.f;
        float e10 = v1 ? __expf(10.f * s10) : 0.f;
        float e11 = v1 ? __expf(10.f * s11) : 0.f;
        colSum[2 * nb]     = e00 + e10;
        colSum[2 * nb + 1] = e01 + e11;
        if (n0 == bp) { if (pm0) posAcc += e00; if (pm1) posAcc += e10; }
        if (n1 == bp) { if (pm0) posAcc += e01; if (pm1) posAcc += e11; }
        if (w00) { g_sTop[t0 * BB + n0] = s00; g_sTop[t0 * BB + n1] = s01; }
        if (w01) { g_sTop[t1 * BB + n0] = s00; g_sTop[t1 * BB + n1] = s01; }
        if (w10) { g_sTop[t0 * BB + n0] = s10; g_sTop[t0 * BB + n1] = s11; }
        if (w11) { g_sTop[t1 * BB + n0] = s10; g_sTop[t1 * BB + n1] = s11; }
    }
    // reduce cols across the 8 lanes with same tg
    #pragma unroll
    for (int o = 4; o <= 16; o <<= 1) {
        #pragma unroll
        for (int i = 0; i < 16; i++)
            colSum[i] += __shfl_xor_sync(0xffffffffu, colSum[i], o);
    }
    if (lane < 4) {
        #pragma unroll
        for (int nb = 0; nb < 8; nb++) {
            partQ[wid][nb * 8 + lane * 2]     = colSum[2 * nb];
            partQ[wid][nb * 8 + lane * 2 + 1] = colSum[2 * nb + 1];
        }
    }
    red[tid] = posAcc;
    __syncthreads();

    int blk = bp * NTILE + tileIdx;
    if (tid < BB) {
        float s = 0.f;
        #pragma unroll
        for (int w = 0; w < 8; w++) s += partQ[w][tid];
        g_totQpart[tid * NBLK + blk] = s;   // transposed: [q][blk]
    }
    for (int s = 128; s > 0; s >>= 1) {
        if (tid < s) red[tid] += red[tid + s];
        __syncthreads();
    }
    if (tid == 0) g_posQpart[blk] = red[0];
    if (tid < 2) {
        const float* src = tid ? nb1s : nb0s;
        float s = 0.f;
        for (int pp = 0; pp < TPL; pp++) s += src[pp];
        g_negIpart[blk * 2 + tid] = s;
    }
}

// ---------------- parallel reduction of totQ partials ----------------
__global__ void k_reduce() {
    int q = blockIdx.x, tid = threadIdx.x;  // 256 threads
    __shared__ float red[256];
    float s = 0.f;
    for (int blk = tid; blk < NBLK; blk += 256) s += g_totQpart[q * NBLK + blk];
    red[tid] = s;
    __syncthreads();
    for (int st = 128; st > 0; st >>= 1) {
        if (tid < st) red[tid] += red[tid + st];
        __syncthreads();
    }
    if (tid == 0) g_totQ[q] = red[0];
}

// ---------------- final: assemble the 4 losses ----------------
__global__ void k_final(float* __restrict__ out) {
    __shared__ float totQ[BB], posQ[BB], negI[TT];
    __shared__ float red[256];
    int tid = threadIdx.x;  // 256

    if (tid < BB) {
        totQ[tid] = g_totQ[tid];
        float sp = 0.f;
        for (int ti = 0; ti < NTILE; ti++) sp += g_posQpart[tid * NTILE + ti];
        posQ[tid] = sp;
    }
    if (tid < TT) {
        int b = tid >> 1, j = tid & 1;
        float s = 0.f;
        for (int ti = 0; ti < NTILE; ti++) s += g_negIpart[(b * NTILE + ti) * 2 + j];
        negI[tid] = s;
    }
    __syncthreads();

    float vals[4] = {0.f, 0.f, 0.f, 0.f};
    if (tid < TT) {
        int b = tid >> 1;
        float pos = g_sTop[tid * BB + b];
        float pe = __expf(10.f * pos);
        float ns = 0.f;
        for (int q = 0; q < BB; q++)
            if (q != b) ns += __expf(10.f * g_sTop[tid * BB + q]);
        vals[0] = -(10.f * pos - logf(pe + ns));
        vals[1] = -(10.f * pos - logf(pe + (totQ[b] - posQ[b])));
        float inv0 = 1.f / fmaxf(sqrtf(g_norm2k[2 * b]), 1e-12f);
        float inv1 = 1.f / fmaxf(sqrtf(g_norm2k[2 * b + 1]), 1e-12f);
        float crossn = g_cross[b] * inv0 * inv1;
        float invt = (tid & 1) ? inv1 : inv0;
        float selfn = g_norm2k[tid] * invt * invt;
        float nI = negI[tid];
        vals[2] = -(10.f * selfn  - logf(__expf(10.f * selfn)  + nI))
                + -(10.f * crossn - logf(__expf(10.f * crossn) + nI));
        float posq = g_qs[b * TT + tid];
        float nsq = 0.f;
        for (int t2 = 0; t2 < TT; t2++)
            if ((t2 >> 1) != b) nsq += __expf(10.f * g_qs[b * TT + t2]);
        vals[3] = -(10.f * posq - logf(__expf(10.f * posq) + nsq));
    }
    const float divi[4] = {128.f, 128.f, 256.f, 128.f};
    for (int m = 0; m < 4; m++) {
        red[tid] = vals[m];
        __syncthreads();
        for (int s = 128; s > 0; s >>= 1) {
            if (tid < s) red[tid] += red[tid + s];
            __syncthreads();
        }
        if (tid == 0) out[m] = red[0] / divi[m];
        __syncthreads();
    }
}

// ---------------- launch (k_main 4th for the profile window) ----------------
extern "C" void kernel_launch(void* const* d_in, const int* in_sizes, int n_in,
                              void* d_out, int out_size) {
    const float* vid    = (const float*)d_in[0];
    const float* qf     = (const float*)d_in[1];
    const float* sf     = (const float*)d_in[2];
    const float* iou2d  = (const float*)d_in[3];
    const float* iou2ds = (const float*)d_in[4];
    (void)in_sizes; (void)n_in; (void)out_size;

    cudaFuncSetAttribute(k_main, cudaFuncAttributeMaxDynamicSharedMemorySize, DYN_SMEM);

    k_topkstats<<<BB, 256>>>(iou2ds, vid);
    k_norms    <<<BB + TT, 256>>>(qf, sf);
    k_qs       <<<BB, 256>>>();
    k_main     <<<dim3(NTILE, BB), 256, DYN_SMEM>>>(vid, iou2d);
    k_reduce   <<<BB, 256>>>();
    k_final    <<<1, 256>>>((float*)d_out);
}

// round 14
// speedup vs baseline: 1.1782x; 1.0136x over previous
#include <cuda_runtime.h>
#include <cuda_bf16.h>
#include <math.h>
#include <stdint.h>

// Problem constants (fixed by setup_inputs)
#define BB 64      // batch
#define CC 256     // channels
#define DD 64      // 2D map side
#define TT 128     // total sentences (B * n, n = 2)
#define PP 2080    // triu proposals
#define TPL 128    // proposals per tile (= GEMM M)
#define NTILE 17   // ceil(PP / TPL)
#define NBLK (BB * NTILE)
#define KCH 32     // K floats per chunk
#define NCHUNK (CC / KCH)  // 8
#define VR 40      // smem row stride in bf16 (80B rows; conflict-free ldmatrix)

// per buffer (bf16 elems): Vh 128*40=5120, Vl 5120, Qh 64*40=2560, Ql 2560
#define BUF_ELEMS 15360
#define DYN_SMEM (2 * BUF_ELEMS * 2)   // 61440 B

// ---------------- scratch (device globals; fully overwritten every launch) ---
__device__ int   g_pk[TT];               // argmax p (triu order) per t
__device__ int   g_pkflat[TT];           // flat r*64+c position
__device__ float g_qn[BB * CC];          // normalized query feats
__device__ __nv_bfloat16 g_qbh[BB * CC]; // bf16 hi of qn
__device__ __nv_bfloat16 g_qbl[BB * CC]; // bf16 lo of qn
__device__ float g_sn[TT * CC];          // normalized sentence feats
__device__ float g_norm2k[TT];           // |v[b', pos_k(t)]|^2  (written by k_main tile 0)
__device__ float g_cross[BB];            // vk0 . vk1 raw dot    (written by k_main tile 0)
__device__ float g_sTop[TT * BB];        // cosine(topk_vf[t], qf_n[b])
__device__ float g_qs[BB * TT];          // qf_n[b] . sf_n[t']
__device__ float g_totQpart[BB * NBLK];  // TRANSPOSED: [q][blk]
__device__ float g_totQ[BB];
__device__ float g_posQpart[NBLK];
__device__ float g_negIpart[NBLK * 2];

// ---------------- mma.sync + ldmatrix wrappers ----------------
__device__ __forceinline__ void mma16816(float* d,
                                         uint32_t a0, uint32_t a1,
                                         uint32_t a2, uint32_t a3,
                                         uint32_t b0, uint32_t b1) {
    asm volatile(
        "mma.sync.aligned.m16n8k16.row.col.f32.bf16.bf16.f32 "
        "{%0,%1,%2,%3}, {%4,%5,%6,%7}, {%8,%9}, {%0,%1,%2,%3};"
        : "+f"(d[0]), "+f"(d[1]), "+f"(d[2]), "+f"(d[3])
        : "r"(a0), "r"(a1), "r"(a2), "r"(a3), "r"(b0), "r"(b1));
}

__device__ __forceinline__ void ldsm_x4(uint32_t& r0, uint32_t& r1,
                                        uint32_t& r2, uint32_t& r3, uint32_t a) {
    asm volatile("ldmatrix.sync.aligned.m8n8.x4.shared.b16 {%0,%1,%2,%3}, [%4];"
                 : "=r"(r0), "=r"(r1), "=r"(r2), "=r"(r3) : "r"(a));
}

__device__ __forceinline__ uint32_t bf16pair(float lo, float hi) {
    __nv_bfloat162 h2(__float2bfloat16(lo), __float2bfloat16(hi));
    return *(uint32_t*)&h2;
}

// ---------------- topk (K=1), one t per block, shuffle argmax ----------------
__global__ void k_topk(const float* __restrict__ iou2ds) {
    int t = blockIdx.x, tid = threadIdx.x, lane = tid & 31, w = tid >> 5;
    const float4* row = (const float4*)(iou2ds + (size_t)t * (DD * DD));
    float best = -1e30f; int bf = 0x3fffffff;
    #pragma unroll
    for (int i = 0; i < 4; i++) {
        int v = tid + i * 256;
        float4 x = row[v];
        int f0 = v * 4;
        float vals[4] = {x.x, x.y, x.z, x.w};
        #pragma unroll
        for (int e = 0; e < 4; e++) {
            int f = f0 + e, r = f >> 6, c = f & 63;
            if (c >= r && vals[e] > best) { best = vals[e]; bf = f; }
        }
    }
    #pragma unroll
    for (int o = 16; o > 0; o >>= 1) {
        float ov = __shfl_xor_sync(0xffffffffu, best, o);
        int   oi = __shfl_xor_sync(0xffffffffu, bf, o);
        if (ov > best || (ov == best && oi < bf)) { best = ov; bf = oi; }
    }
    __shared__ float sv[8]; __shared__ int si[8];
    if (lane == 0) { sv[w] = best; si[w] = bf; }
    __syncthreads();
    if (w == 0) {
        float b2 = (lane < 8) ? sv[lane] : -1e30f;
        int   i2 = (lane < 8) ? si[lane] : 0x3fffffff;
        #pragma unroll
        for (int o = 4; o > 0; o >>= 1) {
            float ov = __shfl_xor_sync(0xffffffffu, b2, o);
            int   oi = __shfl_xor_sync(0xffffffffu, i2, o);
            if (ov > b2 || (ov == b2 && oi < i2)) { b2 = ov; i2 = oi; }
        }
        if (lane == 0) {
            int f = i2, r = f >> 6, c = f & 63;
            g_pk[t] = r * 64 - (r * (r - 1)) / 2 + (c - r);
            g_pkflat[t] = f;
        }
    }
}

// ---------------- row normalization (fused q + s) ----------------
__device__ __forceinline__ float blk_sumsq(float v) {
    float s = v * v;
    for (int o = 16; o > 0; o >>= 1) s += __shfl_xor_sync(0xffffffffu, s, o);
    __shared__ float ws[8];
    int tid = threadIdx.x;
    if ((tid & 31) == 0) ws[tid >> 5] = s;
    __syncthreads();
    return ws[0] + ws[1] + ws[2] + ws[3] + ws[4] + ws[5] + ws[6] + ws[7];
}

__global__ void k_norms(const float* __restrict__ q, const float* __restrict__ s) {
    int row = blockIdx.x, tid = threadIdx.x;
    if (row < BB) {
        float v = q[row * CC + tid];
        float inv = 1.0f / fmaxf(sqrtf(blk_sumsq(v)), 1e-12f);
        float nv = v * inv;
        g_qn[row * CC + tid] = nv;
        __nv_bfloat16 h = __float2bfloat16(nv);
        g_qbh[row * CC + tid] = h;
        g_qbl[row * CC + tid] = __float2bfloat16(nv - __bfloat162float(h));
    } else {
        int r = row - BB;
        float v = s[r * CC + tid];
        float inv = 1.0f / fmaxf(sqrtf(blk_sumsq(v)), 1e-12f);
        g_sn[r * CC + tid] = v * inv;
    }
}

// ---------------- qf_n @ sf_n^T (tiny) ----------------
__global__ void k_qs() {
    int b = blockIdx.x, tid = threadIdx.x;
    __shared__ float qsh[CC];
    qsh[tid] = g_qn[b * CC + tid];
    __syncthreads();
    int w = tid >> 5, lane = tid & 31;
    for (int t2 = w; t2 < TT; t2 += 8) {
        float a = 0.f;
        for (int c = lane; c < CC; c += 32) a += qsh[c] * g_sn[t2 * CC + c];
        for (int o = 16; o > 0; o >>= 1) a += __shfl_xor_sync(0xffffffffu, a, o);
        if (lane == 0) g_qs[b * TT + t2] = a;
    }
}

// ---------------- main fused pass: pipelined mma.sync + ldmatrix ------------
// grid (NTILE, BB), 256 threads (8 warps). Double-buffered smem tiles,
// distance-2 register-prefetched gather (pfA/pfB ping-pong) overlapping MMA.
// vk-stats (norms + cross) computed in-block; tile 0 publishes for k_final.
__global__ void __launch_bounds__(256, 2) k_main(const float* __restrict__ vid,
                                                 const float* __restrict__ iou2d) {
    extern __shared__ __align__(16) char dyn[];
    __nv_bfloat16* sbase = (__nv_bfloat16*)dyn;
    uint32_t sAddr = (uint32_t)__cvta_generic_to_shared(sbase);

    __shared__ float vk0s[CC], vk1s[CC];
    __shared__ int   posArr[TPL];
    __shared__ float ioul[TPL], invnS[TPL];
    __shared__ float statA[256], stat0[256], stat1[256];
    __shared__ float partQ[8][64];
    __shared__ float red[256];
    __shared__ float nb0s[TPL], nb1s[TPL];
    __shared__ float sred[3][8];
    __shared__ float invk01[2];

    int tileIdx = blockIdx.x, bp = blockIdx.y;
    int p0 = tileIdx * TPL;
    int tid = threadIdx.x, wid = tid >> 5, lane = tid & 31;

    const float* vb = vid + (size_t)bp * CC * (DD * DD);
    int t0 = 2 * bp, t1 = t0 + 1;
    int pkI0 = g_pk[t0], pkI1 = g_pk[t1];
    int pf0 = g_pkflat[t0], pf1 = g_pkflat[t1];
    float vv0 = vb[(size_t)tid * (DD * DD) + pf0];
    float vv1 = vb[(size_t)tid * (DD * DD) + pf1];
    vk0s[tid] = vv0;
    vk1s[tid] = vv1;
    // vk stats partials (3 reductions over C, from the just-loaded regs)
    {
        float q0 = vv0 * vv0, q1 = vv1 * vv1, qc = vv0 * vv1;
        #pragma unroll
        for (int o = 16; o > 0; o >>= 1) {
            q0 += __shfl_xor_sync(0xffffffffu, q0, o);
            q1 += __shfl_xor_sync(0xffffffffu, q1, o);
            qc += __shfl_xor_sync(0xffffffffu, qc, o);
        }
        if (lane == 0) { sred[0][wid] = q0; sred[1][wid] = q1; sred[2][wid] = qc; }
    }

    if (tid < TPL) {
        int pg = p0 + tid;
        int pc = pg < PP ? pg : PP - 1;  // clamp; masked in epilogue
        int r = (int)(64.5f - sqrtf(64.5f * 64.5f - 2.0f * (float)pc));
        while (r > 0  && r * 64 - (r * (r - 1)) / 2 > pc) r--;
        while (r < 63 && (r + 1) * 64 - ((r + 1) * r) / 2 <= pc) r++;
        int start = r * 64 - (r * (r - 1)) / 2;
        int pos = r * 64 + (r + (pc - start));
        posArr[tid] = pos;
        ioul[tid] = iou2d[bp * (DD * DD) + pos];
    }
    __syncthreads();

    if (tid == 0) {
        float n0 = 0, n1 = 0, cx = 0;
        #pragma unroll
        for (int w = 0; w < 8; w++) { n0 += sred[0][w]; n1 += sred[1][w]; cx += sred[2][w]; }
        invk01[0] = 1.0f / fmaxf(sqrtf(n0), 1e-12f);
        invk01[1] = 1.0f / fmaxf(sqrtf(n1), 1e-12f);
        if (tileIdx == 0) {
            g_norm2k[t0] = n0; g_norm2k[t1] = n1; g_cross[bp] = cx;
        }
    }
    // (invk01 consumed only after in-loop __syncthreads barriers)

    int p = tid & 127, kh = tid >> 7;       // gather role: (proposal, k-half of 16)
    const float* gp = vb + posArr[p];
    float an = 0.f, a0 = 0.f, a1 = 0.f;

    float acc[8][4] = {};                   // 8 n-blocks x 4 f32
    int g = lane >> 2, tg = lane & 3;       // fragment group ids

    // ldmatrix per-lane address offsets (bytes)
    uint32_t aoffA = ((uint32_t)((wid * 16 + (lane & 15)) * VR) +
                      ((lane >> 4) << 3)) * 2u;
    uint32_t boffB = ((uint32_t)(((lane & 7) + ((lane & 16) ? 8 : 0)) * VR) +
                      ((lane & 8) ? 8 : 0)) * 2u;

    // prefetch chunks 0 and 1 (distance-2 ping-pong)
    float pfA[16], pfB[16];
    #pragma unroll
    for (int j = 0; j < 16; j++) {
        pfA[j] = gp[(size_t)(0 * KCH + kh * 16 + j) * (DD * DD)];
        pfB[j] = gp[(size_t)(1 * KCH + kh * 16 + j) * (DD * DD)];
    }

#define CHUNK_BODY(C, PF) do {                                                \
    int kb = (C) * KCH;                                                       \
    int buf = (C) & 1;                                                        \
    __nv_bfloat16* Vh = sbase + buf * BUF_ELEMS;                              \
    __nv_bfloat16* Vl = Vh + 5120;                                            \
    __nv_bfloat16* Qh = Vh + 10240;                                           \
    __nv_bfloat16* Ql = Vh + 12800;                                           \
    uint32_t sV = sAddr + (uint32_t)buf * (BUF_ELEMS * 2u);                   \
    _Pragma("unroll")                                                         \
    for (int j = 0; j < 16; j += 4) {                                         \
        int k = kb + kh * 16 + j;                                             \
        float v0 = PF[j], v1 = PF[j + 1], v2 = PF[j + 2], v3 = PF[j + 3];     \
        an += v0 * v0 + v1 * v1 + v2 * v2 + v3 * v3;                          \
        a0 += v0 * vk0s[k] + v1 * vk0s[k + 1] + v2 * vk0s[k + 2] + v3 * vk0s[k + 3]; \
        a1 += v0 * vk1s[k] + v1 * vk1s[k + 1] + v2 * vk1s[k + 2] + v3 * vk1s[k + 3]; \
        __nv_bfloat16 h0 = __float2bfloat16(v0), h1 = __float2bfloat16(v1);   \
        __nv_bfloat16 h2 = __float2bfloat16(v2), h3 = __float2bfloat16(v3);   \
        uint2 hb, lb;                                                         \
        { __nv_bfloat162 t01(h0, h1), t23(h2, h3);                            \
          hb.x = *(uint32_t*)&t01; hb.y = *(uint32_t*)&t23; }                 \
        lb.x = bf16pair(v0 - __bfloat162float(h0), v1 - __bfloat162float(h1)); \
        lb.y = bf16pair(v2 - __bfloat162float(h2), v3 - __bfloat162float(h3)); \
        int so = p * VR + kh * 16 + j;                                        \
        *(uint2*)&Vh[so] = hb;                                                \
        *(uint2*)&Vl[so] = lb;                                                \
    }                                                                         \
    _Pragma("unroll")                                                         \
    for (int i = 0; i < 4; i++) {                                             \
        int idx = tid + i * 256;                                              \
        int q = idx >> 4, kp = idx & 15;                                      \
        *(uint32_t*)&Qh[q * VR + kp * 2] = *(const uint32_t*)&g_qbh[q * CC + kb + kp * 2]; \
        *(uint32_t*)&Ql[q * VR + kp * 2] = *(const uint32_t*)&g_qbl[q * CC + kb + kp * 2]; \
    }                                                                         \
    __syncthreads();                                                          \
    if ((C) + 2 < NCHUNK) {                                                   \
        int kn = ((C) + 2) * KCH + kh * 16;                                   \
        _Pragma("unroll")                                                     \
        for (int j = 0; j < 16; j++)                                          \
            PF[j] = gp[(size_t)(kn + j) * (DD * DD)];                         \
    }                                                                         \
    _Pragma("unroll")                                                         \
    for (int ks = 0; ks < 2; ks++) {                                          \
        uint32_t kadd = (uint32_t)(ks * 32);                                  \
        uint32_t ah0, ah1, ah2, ah3, al0, al1, al2, al3;                      \
        ldsm_x4(ah0, ah1, ah2, ah3, sV + aoffA + kadd);                       \
        ldsm_x4(al0, al1, al2, al3, sV + aoffA + kadd + 10240u);              \
        _Pragma("unroll")                                                     \
        for (int j = 0; j < 4; j++) {                                         \
            uint32_t bq = sV + 20480u + boffB + (uint32_t)(j * (16 * VR * 2)) + kadd; \
            uint32_t bh0, bh1, bh2, bh3, bl0, bl1, bl2, bl3;                  \
            ldsm_x4(bh0, bh1, bh2, bh3, bq);                                  \
            ldsm_x4(bl0, bl1, bl2, bl3, bq + 5120u);                          \
            mma16816(acc[2 * j],     ah0, ah1, ah2, ah3, bh0, bh1);           \
            mma16816(acc[2 * j],     ah0, ah1, ah2, ah3, bl0, bl1);           \
            mma16816(acc[2 * j],     al0, al1, al2, al3, bh0, bh1);           \
            mma16816(acc[2 * j + 1], ah0, ah1, ah2, ah3, bh2, bh3);           \
            mma16816(acc[2 * j + 1], ah0, ah1, ah2, ah3, bl2, bl3);           \
            mma16816(acc[2 * j + 1], al0, al1, al2, al3, bh2, bh3);           \
        }                                                                     \
    }                                                                         \
} while (0)

    #pragma unroll
    for (int c = 0; c < NCHUNK; c += 2) {
        CHUNK_BODY(c, pfA);
        CHUNK_BODY(c + 1, pfB);
    }
#undef CHUNK_BODY

    // ---- stats combine (p owned by 2 threads: kh halves) ----
    statA[tid] = an; stat0[tid] = a0; stat1[tid] = a1;
    __syncthreads();
    if (tid < TPL) {
        float n2 = statA[tid] + statA[tid + 128];
        float inv = 1.0f / fmaxf(sqrtf(n2), 1e-12f);
        invnS[tid] = inv;
        float i0 = stat0[tid] + stat0[tid + 128];
        float i1 = stat1[tid] + stat1[tid + 128];
        bool negm = (p0 + tid < PP) && (ioul[tid] < 0.5f);
        nb0s[tid] = negm ? __expf(10.0f * i0 * inv * invk01[0]) : 0.f;
        nb1s[tid] = negm ? __expf(10.0f * i1 * inv * invk01[1]) : 0.f;
    }
    __syncthreads();

    // ---- epilogue: scores -> exp -> column partials ----
    int rl0 = wid * 16 + g, rl1 = rl0 + 8;
    int pg0 = p0 + rl0, pg1 = p0 + rl1;
    bool v0 = pg0 < PP, v1 = pg1 < PP;
    float in0 = invnS[rl0], in1 = invnS[rl1];
    bool pm0 = v0 && (ioul[rl0] > 0.5f), pm1 = v1 && (ioul[rl1] > 0.5f);
    bool w00 = (pg0 == pkI0), w01 = (pg0 == pkI1);
    bool w10 = (pg1 == pkI0), w11 = (pg1 == pkI1);

    float colSum[16];
    float posAcc = 0.f;
    #pragma unroll
    for (int nb = 0; nb < 8; nb++) {
        int n0 = nb * 8 + tg * 2, n1 = n0 + 1;
        float s00 = acc[nb][0] * in0, s01 = acc[nb][1] * in0;
        float s10 = acc[nb][2] * in1, s11 = acc[nb][3] * in1;
        float e00 = v0 ? __expf(10.f * s00) : 0.f;
        float e01 = v0 ? __expf(10.f * s01) : 0.f;
        float e10 = v1 ? __expf(10.f * s10) : 0.f;
        float e11 = v1 ? __expf(10.f * s11) : 0.f;
        colSum[2 * nb]     = e00 + e10;
        colSum[2 * nb + 1] = e01 + e11;
        if (n0 == bp) { if (pm0) posAcc += e00; if (pm1) posAcc += e10; }
        if (n1 == bp) { if (pm0) posAcc += e01; if (pm1) posAcc += e11; }
        if (w00) { g_sTop[t0 * BB + n0] = s00; g_sTop[t0 * BB + n1] = s01; }
        if (w01) { g_sTop[t1 * BB + n0] = s00; g_sTop[t1 * BB + n1] = s01; }
        if (w10) { g_sTop[t0 * BB + n0] = s10; g_sTop[t0 * BB + n1] = s11; }
        if (w11) { g_sTop[t1 * BB + n0] = s10; g_sTop[t1 * BB + n1] = s11; }
    }
    // reduce cols across the 8 lanes with same tg
    #pragma unroll
    for (int o = 4; o <= 16; o <<= 1) {
        #pragma unroll
        for (int i = 0; i < 16; i++)
            colSum[i] += __shfl_xor_sync(0xffffffffu, colSum[i], o);
    }
    if (lane < 4) {
        #pragma unroll
        for (int nb = 0; nb < 8; nb++) {
            partQ[wid][nb * 8 + lane * 2]     = colSum[2 * nb];
            partQ[wid][nb * 8 + lane * 2 + 1] = colSum[2 * nb + 1];
        }
    }
    red[tid] = posAcc;
    __syncthreads();

    int blk = bp * NTILE + tileIdx;
    if (tid < BB) {
        float s = 0.f;
        #pragma unroll
        for (int w = 0; w < 8; w++) s += partQ[w][tid];
        g_totQpart[tid * NBLK + blk] = s;   // transposed: [q][blk]
    }
    for (int s = 128; s > 0; s >>= 1) {
        if (tid < s) red[tid] += red[tid + s];
        __syncthreads();
    }
    if (tid == 0) g_posQpart[blk] = red[0];
    if (tid < 2) {
        const float* src = tid ? nb1s : nb0s;
        float s = 0.f;
        for (int pp = 0; pp < TPL; pp++) s += src[pp];
        g_negIpart[blk * 2 + tid] = s;
    }
}

// ---------------- parallel reduction of totQ partials ----------------
__global__ void k_reduce() {
    int q = blockIdx.x, tid = threadIdx.x;  // 256 threads
    __shared__ float red[256];
    float s = 0.f;
    for (int blk = tid; blk < NBLK; blk += 256) s += g_totQpart[q * NBLK + blk];
    red[tid] = s;
    __syncthreads();
    for (int st = 128; st > 0; st >>= 1) {
        if (tid < st) red[tid] += red[tid + st];
        __syncthreads();
    }
    if (tid == 0) g_totQ[q] = red[0];
}

// ---------------- final: assemble the 4 losses ----------------
__global__ void k_final(float* __restrict__ out) {
    __shared__ float totQ[BB], posQ[BB], negI[TT];
    __shared__ float red[256];
    int tid = threadIdx.x;  // 256

    if (tid < BB) {
        totQ[tid] = g_totQ[tid];
        float sp = 0.f;
        for (int ti = 0; ti < NTILE; ti++) sp += g_posQpart[tid * NTILE + ti];
        posQ[tid] = sp;
    }
    if (tid < TT) {
        int b = tid >> 1, j = tid & 1;
        float s = 0.f;
        for (int ti = 0; ti < NTILE; ti++) s += g_negIpart[(b * NTILE + ti) * 2 + j];
        negI[tid] = s;
    }
    __syncthreads();

    float vals[4] = {0.f, 0.f, 0.f, 0.f};
    if (tid < TT) {
        int b = tid >> 1;
        float pos = g_sTop[tid * BB + b];
        float pe = __expf(10.f * pos);
        float ns = 0.f;
        for (int q = 0; q < BB; q++)
            if (q != b) ns += __expf(10.f * g_sTop[tid * BB + q]);
        vals[0] = -(10.f * pos - logf(pe + ns));
        vals[1] = -(10.f * pos - logf(pe + (totQ[b] - posQ[b])));
        float inv0 = 1.f / fmaxf(sqrtf(g_norm2k[2 * b]), 1e-12f);
        float inv1 = 1.f / fmaxf(sqrtf(g_norm2k[2 * b + 1]), 1e-12f);
        float crossn = g_cross[b] * inv0 * inv1;
        float invt = (tid & 1) ? inv1 : inv0;
        float selfn = g_norm2k[tid] * invt * invt;
        float nI = negI[tid];
        vals[2] = -(10.f * selfn  - logf(__expf(10.f * selfn)  + nI))
                + -(10.f * crossn - logf(__expf(10.f * crossn) + nI));
        float posq = g_qs[b * TT + tid];
        float nsq = 0.f;
        for (int t2 = 0; t2 < TT; t2++)
            if ((t2 >> 1) != b) nsq += __expf(10.f * g_qs[b * TT + t2]);
        vals[3] = -(10.f * posq - logf(__expf(10.f * posq) + nsq));
    }
    const float divi[4] = {128.f, 128.f, 256.f, 128.f};
    for (int m = 0; m < 4; m++) {
        red[tid] = vals[m];
        __syncthreads();
        for (int s = 128; s > 0; s >>= 1) {
            if (tid < s) red[tid] += red[tid + s];
            __syncthreads();
        }
        if (tid == 0) out[m] = red[0] / divi[m];
        __syncthreads();
    }
}

// ---------------- launch (k_main 4th for the profile window) ----------------
extern "C" void kernel_launch(void* const* d_in, const int* in_sizes, int n_in,
                              void* d_out, int out_size) {
    const float* vid    = (const float*)d_in[0];
    const float* qf     = (const float*)d_in[1];
    const float* sf     = (const float*)d_in[2];
    const float* iou2d  = (const float*)d_in[3];
    const float* iou2ds = (const float*)d_in[4];
    (void)in_sizes; (void)n_in; (void)out_size;

    cudaFuncSetAttribute(k_main, cudaFuncAttributeMaxDynamicSharedMemorySize, DYN_SMEM);

    k_topk  <<<TT, 256>>>(iou2ds);
    k_norms <<<BB + TT, 256>>>(qf, sf);
    k_qs    <<<BB, 256>>>();
    k_main  <<<dim3(NTILE, BB), 256, DYN_SMEM>>>(vid, iou2d);
    k_reduce<<<BB, 256>>>();
    k_final <<<1, 256>>>((float*)d_out);
}

// round 15
// speedup vs baseline: 1.2189x; 1.0346x over previous
#include <cuda_runtime.h>
#include <cuda_bf16.h>
#include <math.h>
#include <stdint.h>

// Problem constants (fixed by setup_inputs)
#define BB 64      // batch
#define CC 256     // channels
#define DD 64      // 2D map side
#define TT 128     // total sentences (B * n, n = 2)
#define PP 2080    // triu proposals
#define TPL 128    // proposals per tile (= GEMM M)
#define NTILE 17   // ceil(PP / TPL)
#define NBLK (BB * NTILE)
#define KCH 32     // K floats per chunk
#define NCHUNK (CC / KCH)  // 8
#define VR 40      // smem row stride in bf16 (80B rows; conflict-free ldmatrix)

// per buffer (bf16 elems): Vh 128*40=5120, Vl 5120, Qh 64*40=2560, Ql 2560
#define BUF_ELEMS 15360
#define DYN_SMEM (2 * BUF_ELEMS * 2)   // 61440 B

// ---------------- scratch (device globals; fully overwritten every launch) ---
__device__ int   g_pk[TT];               // argmax p (triu order) per t
__device__ int   g_pkflat[TT];           // flat r*64+c position
__device__ float g_qn[BB * CC];          // normalized query feats
__device__ __nv_bfloat16 g_qbh[BB * CC]; // bf16 hi of qn
__device__ __nv_bfloat16 g_qbl[BB * CC]; // bf16 lo of qn
__device__ float g_sn[TT * CC];          // normalized sentence feats
__device__ float g_norm2k[TT];           // |v[b', pos_k(t)]|^2  (written by k_main tile 0)
__device__ float g_cross[BB];            // vk0 . vk1 raw dot    (written by k_main tile 0)
__device__ float g_sTop[TT * BB];        // cosine(topk_vf[t], qf_n[b])
__device__ float g_qs[BB * TT];          // qf_n[b] . sf_n[t']
__device__ float g_totQpart[BB * NBLK];  // TRANSPOSED: [q][blk]
__device__ float g_totQ[BB];
__device__ float g_posQpart[NBLK];
__device__ float g_negIpart[NBLK * 2];

// ---------------- mma.sync + ldmatrix wrappers ----------------
__device__ __forceinline__ void mma16816(float* d,
                                         uint32_t a0, uint32_t a1,
                                         uint32_t a2, uint32_t a3,
                                         uint32_t b0, uint32_t b1) {
    asm volatile(
        "mma.sync.aligned.m16n8k16.row.col.f32.bf16.bf16.f32 "
        "{%0,%1,%2,%3}, {%4,%5,%6,%7}, {%8,%9}, {%0,%1,%2,%3};"
        : "+f"(d[0]), "+f"(d[1]), "+f"(d[2]), "+f"(d[3])
        : "r"(a0), "r"(a1), "r"(a2), "r"(a3), "r"(b0), "r"(b1));
}

__device__ __forceinline__ void ldsm_x4(uint32_t& r0, uint32_t& r1,
                                        uint32_t& r2, uint32_t& r3, uint32_t a) {
    asm volatile("ldmatrix.sync.aligned.m8n8.x4.shared.b16 {%0,%1,%2,%3}, [%4];"
                 : "=r"(r0), "=r"(r1), "=r"(r2), "=r"(r3) : "r"(a));
}

__device__ __forceinline__ uint32_t bf16pair(float lo, float hi) {
    __nv_bfloat162 h2(__float2bfloat16(lo), __float2bfloat16(hi));
    return *(uint32_t*)&h2;
}

// ---------------- topk (K=1), one t per block, shuffle argmax ----------------
__global__ void k_topk(const float* __restrict__ iou2ds) {
    int t = blockIdx.x, tid = threadIdx.x, lane = tid & 31, w = tid >> 5;
    const float4* row = (const float4*)(iou2ds + (size_t)t * (DD * DD));
    float best = -1e30f; int bf = 0x3fffffff;
    #pragma unroll
    for (int i = 0; i < 4; i++) {
        int v = tid + i * 256;
        float4 x = row[v];
        int f0 = v * 4;
        float vals[4] = {x.x, x.y, x.z, x.w};
        #pragma unroll
        for (int e = 0; e < 4; e++) {
            int f = f0 + e, r = f >> 6, c = f & 63;
            if (c >= r && vals[e] > best) { best = vals[e]; bf = f; }
        }
    }
    #pragma unroll
    for (int o = 16; o > 0; o >>= 1) {
        float ov = __shfl_xor_sync(0xffffffffu, best, o);
        int   oi = __shfl_xor_sync(0xffffffffu, bf, o);
        if (ov > best || (ov == best && oi < bf)) { best = ov; bf = oi; }
    }
    __shared__ float sv[8]; __shared__ int si[8];
    if (lane == 0) { sv[w] = best; si[w] = bf; }
    __syncthreads();
    if (w == 0) {
        float b2 = (lane < 8) ? sv[lane] : -1e30f;
        int   i2 = (lane < 8) ? si[lane] : 0x3fffffff;
        #pragma unroll
        for (int o = 4; o > 0; o >>= 1) {
            float ov = __shfl_xor_sync(0xffffffffu, b2, o);
            int   oi = __shfl_xor_sync(0xffffffffu, i2, o);
            if (ov > b2 || (ov == b2 && oi < i2)) { b2 = ov; i2 = oi; }
        }
        if (lane == 0) {
            int f = i2, r = f >> 6, c = f & 63;
            g_pk[t] = r * 64 - (r * (r - 1)) / 2 + (c - r);
            g_pkflat[t] = f;
        }
    }
}

// ---------------- row normalization (fused q + s) ----------------
__device__ __forceinline__ float blk_sumsq(float v) {
    float s = v * v;
    for (int o = 16; o > 0; o >>= 1) s += __shfl_xor_sync(0xffffffffu, s, o);
    __shared__ float ws[8];
    int tid = threadIdx.x;
    if ((tid & 31) == 0) ws[tid >> 5] = s;
    __syncthreads();
    return ws[0] + ws[1] + ws[2] + ws[3] + ws[4] + ws[5] + ws[6] + ws[7];
}

__global__ void k_norms(const float* __restrict__ q, const float* __restrict__ s) {
    int row = blockIdx.x, tid = threadIdx.x;
    if (row < BB) {
        float v = q[row * CC + tid];
        float inv = 1.0f / fmaxf(sqrtf(blk_sumsq(v)), 1e-12f);
        float nv = v * inv;
        g_qn[row * CC + tid] = nv;
        __nv_bfloat16 h = __float2bfloat16(nv);
        g_qbh[row * CC + tid] = h;
        g_qbl[row * CC + tid] = __float2bfloat16(nv - __bfloat162float(h));
    } else {
        int r = row - BB;
        float v = s[r * CC + tid];
        float inv = 1.0f / fmaxf(sqrtf(blk_sumsq(v)), 1e-12f);
        g_sn[r * CC + tid] = v * inv;
    }
}

// ---------------- qf_n @ sf_n^T (tiny) ----------------
__global__ void k_qs() {
    int b = blockIdx.x, tid = threadIdx.x;
    __shared__ float qsh[CC];
    qsh[tid] = g_qn[b * CC + tid];
    __syncthreads();
    int w = tid >> 5, lane = tid & 31;
    for (int t2 = w; t2 < TT; t2 += 8) {
        float a = 0.f;
        for (int c = lane; c < CC; c += 32) a += qsh[c] * g_sn[t2 * CC + c];
        for (int o = 16; o > 0; o >>= 1) a += __shfl_xor_sync(0xffffffffu, a, o);
        if (lane == 0) g_qs[b * TT + t2] = a;
    }
}

// ---------------- main fused pass: pipelined mma.sync + ldmatrix ------------
// grid (NTILE, BB), 256 threads (8 warps). Double-buffered smem tiles,
// distance-1 register-prefetched gather overlapping the MMA (R13 pipeline —
// no reg cap: prefetch MLP needs the registers). vk-stats fused in-block;
// tile 0 publishes norms/cross. Stats vk reads vectorized as float4.
__global__ void __launch_bounds__(256) k_main(const float* __restrict__ vid,
                                              const float* __restrict__ iou2d) {
    extern __shared__ __align__(16) char dyn[];
    __nv_bfloat16* sbase = (__nv_bfloat16*)dyn;
    uint32_t sAddr = (uint32_t)__cvta_generic_to_shared(sbase);

    __shared__ __align__(16) float vk0s[CC];
    __shared__ __align__(16) float vk1s[CC];
    __shared__ int   posArr[TPL];
    __shared__ float ioul[TPL], invnS[TPL];
    __shared__ float statA[256], stat0[256], stat1[256];
    __shared__ float partQ[8][64];
    __shared__ float red[256];
    __shared__ float nb0s[TPL], nb1s[TPL];
    __shared__ float sred[3][8];
    __shared__ float invk01[2];

    int tileIdx = blockIdx.x, bp = blockIdx.y;
    int p0 = tileIdx * TPL;
    int tid = threadIdx.x, wid = tid >> 5, lane = tid & 31;

    const float* vb = vid + (size_t)bp * CC * (DD * DD);
    int t0 = 2 * bp, t1 = t0 + 1;
    int pkI0 = g_pk[t0], pkI1 = g_pk[t1];
    int pf0 = g_pkflat[t0], pf1 = g_pkflat[t1];
    float vv0 = vb[(size_t)tid * (DD * DD) + pf0];
    float vv1 = vb[(size_t)tid * (DD * DD) + pf1];
    vk0s[tid] = vv0;
    vk1s[tid] = vv1;
    // vk stats partials (3 reductions over C, from the just-loaded regs)
    {
        float q0 = vv0 * vv0, q1 = vv1 * vv1, qc = vv0 * vv1;
        #pragma unroll
        for (int o = 16; o > 0; o >>= 1) {
            q0 += __shfl_xor_sync(0xffffffffu, q0, o);
            q1 += __shfl_xor_sync(0xffffffffu, q1, o);
            qc += __shfl_xor_sync(0xffffffffu, qc, o);
        }
        if (lane == 0) { sred[0][wid] = q0; sred[1][wid] = q1; sred[2][wid] = qc; }
    }

    if (tid < TPL) {
        int pg = p0 + tid;
        int pc = pg < PP ? pg : PP - 1;  // clamp; masked in epilogue
        int r = (int)(64.5f - sqrtf(64.5f * 64.5f - 2.0f * (float)pc));
        while (r > 0  && r * 64 - (r * (r - 1)) / 2 > pc) r--;
        while (r < 63 && (r + 1) * 64 - ((r + 1) * r) / 2 <= pc) r++;
        int start = r * 64 - (r * (r - 1)) / 2;
        int pos = r * 64 + (r + (pc - start));
        posArr[tid] = pos;
        ioul[tid] = iou2d[bp * (DD * DD) + pos];
    }
    __syncthreads();

    if (tid == 0) {
        float n0 = 0, n1 = 0, cx = 0;
        #pragma unroll
        for (int w = 0; w < 8; w++) { n0 += sred[0][w]; n1 += sred[1][w]; cx += sred[2][w]; }
        invk01[0] = 1.0f / fmaxf(sqrtf(n0), 1e-12f);
        invk01[1] = 1.0f / fmaxf(sqrtf(n1), 1e-12f);
        if (tileIdx == 0) {
            g_norm2k[t0] = n0; g_norm2k[t1] = n1; g_cross[bp] = cx;
        }
    }
    // (invk01 consumed only after in-loop __syncthreads barriers)

    int p = tid & 127, kh = tid >> 7;       // gather role: (proposal, k-half of 16)
    const float* gp = vb + posArr[p];
    float an = 0.f, a0 = 0.f, a1 = 0.f;

    float acc[8][4] = {};                   // 8 n-blocks x 4 f32
    int g = lane >> 2, tg = lane & 3;       // fragment group ids

    // ldmatrix per-lane address offsets (bytes)
    uint32_t aoffA = ((uint32_t)((wid * 16 + (lane & 15)) * VR) +
                      ((lane >> 4) << 3)) * 2u;
    uint32_t boffB = ((uint32_t)(((lane & 7) + ((lane & 16) ? 8 : 0)) * VR) +
                      ((lane & 8) ? 8 : 0)) * 2u;

    // prefetch chunk 0
    float pf[16];
    #pragma unroll
    for (int j = 0; j < 16; j++)
        pf[j] = gp[(size_t)(kh * 16 + j) * (DD * DD)];

    for (int c = 0; c < NCHUNK; c++) {
        int kb = c * KCH;
        int buf = c & 1;
        __nv_bfloat16* Vh = sbase + buf * BUF_ELEMS;
        __nv_bfloat16* Vl = Vh + 5120;
        __nv_bfloat16* Qh = Vh + 10240;
        __nv_bfloat16* Ql = Vh + 12800;
        uint32_t sV = sAddr + (uint32_t)buf * (BUF_ELEMS * 2u);

        // ---- convert prefetched V -> smem (hi/lo), stats ride along ----
        const float4* vk0v = (const float4*)&vk0s[kb + kh * 16];
        const float4* vk1v = (const float4*)&vk1s[kb + kh * 16];
        #pragma unroll
        for (int j = 0; j < 16; j += 4) {
            float4 w0 = vk0v[j >> 2];
            float4 w1 = vk1v[j >> 2];
            float v0 = pf[j], v1 = pf[j + 1], v2 = pf[j + 2], v3 = pf[j + 3];
            an += v0 * v0 + v1 * v1 + v2 * v2 + v3 * v3;
            a0 += v0 * w0.x + v1 * w0.y + v2 * w0.z + v3 * w0.w;
            a1 += v0 * w1.x + v1 * w1.y + v2 * w1.z + v3 * w1.w;
            __nv_bfloat16 h0 = __float2bfloat16(v0), h1 = __float2bfloat16(v1);
            __nv_bfloat16 h2 = __float2bfloat16(v2), h3 = __float2bfloat16(v3);
            uint2 hb, lb;
            { __nv_bfloat162 t01(h0, h1), t23(h2, h3);
              hb.x = *(uint32_t*)&t01; hb.y = *(uint32_t*)&t23; }
            lb.x = bf16pair(v0 - __bfloat162float(h0), v1 - __bfloat162float(h1));
            lb.y = bf16pair(v2 - __bfloat162float(h2), v3 - __bfloat162float(h3));
            int so = p * VR + kh * 16 + j;
            *(uint2*)&Vh[so] = hb;
            *(uint2*)&Vl[so] = lb;
        }
        // ---- Q tiles: 64 q x 16 u32-pairs each, coalesced (L1-hot) ----
        #pragma unroll
        for (int i = 0; i < 4; i++) {
            int idx = tid + i * 256;          // 0..1023
            int q = idx >> 4, kp = idx & 15;
            *(uint32_t*)&Qh[q * VR + kp * 2] = *(const uint32_t*)&g_qbh[q * CC + kb + kp * 2];
            *(uint32_t*)&Ql[q * VR + kp * 2] = *(const uint32_t*)&g_qbl[q * CC + kb + kp * 2];
        }
        __syncthreads();

        // ---- issue next chunk's gather (overlaps MMA below) ----
        if (c + 1 < NCHUNK) {
            int kn = (c + 1) * KCH + kh * 16;
            #pragma unroll
            for (int j = 0; j < 16; j++)
                pf[j] = gp[(size_t)(kn + j) * (DD * DD)];
        }

        // ---- MMA via ldmatrix: warp w rows w*16.., all 64 cols, 2 k-steps --
        #pragma unroll
        for (int ks = 0; ks < 2; ks++) {
            uint32_t kadd = (uint32_t)(ks * 32);   // 16 bf16 * 2B
            uint32_t ah0, ah1, ah2, ah3, al0, al1, al2, al3;
            ldsm_x4(ah0, ah1, ah2, ah3, sV + aoffA + kadd);
            ldsm_x4(al0, al1, al2, al3, sV + aoffA + kadd + 10240u);  // Vl
            #pragma unroll
            for (int j = 0; j < 4; j++) {
                uint32_t bq = sV + 20480u + boffB + (uint32_t)(j * (16 * VR * 2)) + kadd;
                uint32_t bh0, bh1, bh2, bh3, bl0, bl1, bl2, bl3;
                ldsm_x4(bh0, bh1, bh2, bh3, bq);            // Qh
                ldsm_x4(bl0, bl1, bl2, bl3, bq + 5120u);    // Ql
                mma16816(acc[2 * j],     ah0, ah1, ah2, ah3, bh0, bh1);
                mma16816(acc[2 * j],     ah0, ah1, ah2, ah3, bl0, bl1);
                mma16816(acc[2 * j],     al0, al1, al2, al3, bh0, bh1);
                mma16816(acc[2 * j + 1], ah0, ah1, ah2, ah3, bh2, bh3);
                mma16816(acc[2 * j + 1], ah0, ah1, ah2, ah3, bl2, bl3);
                mma16816(acc[2 * j + 1], al0, al1, al2, al3, bh2, bh3);
            }
        }
        // no trailing barrier: double-buffered; next write targets other buffer.
    }

    // ---- stats combine (p owned by 2 threads: kh halves) ----
    statA[tid] = an; stat0[tid] = a0; stat1[tid] = a1;
    __syncthreads();
    if (tid < TPL) {
        float n2 = statA[tid] + statA[tid + 128];
        float inv = 1.0f / fmaxf(sqrtf(n2), 1e-12f);
        invnS[tid] = inv;
        float i0 = stat0[tid] + stat0[tid + 128];
        float i1 = stat1[tid] + stat1[tid + 128];
        bool negm = (p0 + tid < PP) && (ioul[tid] < 0.5f);
        nb0s[tid] = negm ? __expf(10.0f * i0 * inv * invk01[0]) : 0.f;
        nb1s[tid] = negm ? __expf(10.0f * i1 * inv * invk01[1]) : 0.f;
    }
    __syncthreads();

    // ---- epilogue: scores -> exp -> column partials ----
    int rl0 = wid * 16 + g, rl1 = rl0 + 8;
    int pg0 = p0 + rl0, pg1 = p0 + rl1;
    bool v0 = pg0 < PP, v1 = pg1 < PP;
    float in0 = invnS[rl0], in1 = invnS[rl1];
    bool pm0 = v0 && (ioul[rl0] > 0.5f), pm1 = v1 && (ioul[rl1] > 0.5f);
    bool w00 = (pg0 == pkI0), w01 = (pg0 == pkI1);
    bool w10 = (pg1 == pkI0), w11 = (pg1 == pkI1);

    float colSum[16];
    float posAcc = 0.f;
    #pragma unroll
    for (int nb = 0; nb < 8; nb++) {
        int n0 = nb * 8 + tg * 2, n1 = n0 + 1;
        float s00 = acc[nb][0] * in0, s01 = acc[nb][1] * in0;
        float s10 = acc[nb][2] * in1, s11 = acc[nb][3] * in1;
        float e00 = v0 ? __expf(10.f * s00) : 0.f;
        float e01 = v0 ? __expf(10.f * s01) : 0.f;
        float e10 = v1 ? __expf(10.f * s10) : 0.f;
        float e11 = v1 ? __expf(10.f * s11) : 0.f;
        colSum[2 * nb]     = e00 + e10;
        colSum[2 * nb + 1] = e01 + e11;
        if (n0 == bp) { if (pm0) posAcc += e00; if (pm1) posAcc += e10; }
        if (n1 == bp) { if (pm0) posAcc += e01; if (pm1) posAcc += e11; }
        if (w00) { g_sTop[t0 * BB + n0] = s00; g_sTop[t0 * BB + n1] = s01; }
        if (w01) { g_sTop[t1 * BB + n0] = s00; g_sTop[t1 * BB + n1] = s01; }
        if (w10) { g_sTop[t0 * BB + n0] = s10; g_sTop[t0 * BB + n1] = s11; }
        if (w11) { g_sTop[t1 * BB + n0] = s10; g_sTop[t1 * BB + n1] = s11; }
    }
    // reduce cols across the 8 lanes with same tg
    #pragma unroll
    for (int o = 4; o <= 16; o <<= 1) {
        #pragma unroll
        for (int i = 0; i < 16; i++)
            colSum[i] += __shfl_xor_sync(0xffffffffu, colSum[i], o);
    }
    if (lane < 4) {
        #pragma unroll
        for (int nb = 0; nb < 8; nb++) {
            partQ[wid][nb * 8 + lane * 2]     = colSum[2 * nb];
            partQ[wid][nb * 8 + lane * 2 + 1] = colSum[2 * nb + 1];
        }
    }
    red[tid] = posAcc;
    __syncthreads();

    int blk = bp * NTILE + tileIdx;
    if (tid < BB) {
        float s = 0.f;
        #pragma unroll
        for (int w = 0; w < 8; w++) s += partQ[w][tid];
        g_totQpart[tid * NBLK + blk] = s;   // transposed: [q][blk]
    }
    for (int s = 128; s > 0; s >>= 1) {
        if (tid < s) red[tid] += red[tid + s];
        __syncthreads();
    }
    if (tid == 0) g_posQpart[blk] = red[0];
    if (tid < 2) {
        const float* src = tid ? nb1s : nb0s;
        float s = 0.f;
        for (int pp = 0; pp < TPL; pp++) s += src[pp];
        g_negIpart[blk * 2 + tid] = s;
    }
}

// ---------------- parallel reduction of totQ partials ----------------
__global__ void k_reduce() {
    int q = blockIdx.x, tid = threadIdx.x;  // 256 threads
    __shared__ float red[256];
    float s = 0.f;
    for (int blk = tid; blk < NBLK; blk += 256) s += g_totQpart[q * NBLK + blk];
    red[tid] = s;
    __syncthreads();
    for (int st = 128; st > 0; st >>= 1) {
        if (tid < st) red[tid] += red[tid + st];
        __syncthreads();
    }
    if (tid == 0) g_totQ[q] = red[0];
}

// ---------------- final: assemble the 4 losses ----------------
__global__ void k_final(float* __restrict__ out) {
    __shared__ float totQ[BB], posQ[BB], negI[TT];
    __shared__ float red[256];
    int tid = threadIdx.x;  // 256

    if (tid < BB) {
        totQ[tid] = g_totQ[tid];
        float sp = 0.f;
        for (int ti = 0; ti < NTILE; ti++) sp += g_posQpart[tid * NTILE + ti];
        posQ[tid] = sp;
    }
    if (tid < TT) {
        int b = tid >> 1, j = tid & 1;
        float s = 0.f;
        for (int ti = 0; ti < NTILE; ti++) s += g_negIpart[(b * NTILE + ti) * 2 + j];
        negI[tid] = s;
    }
    __syncthreads();

    float vals[4] = {0.f, 0.f, 0.f, 0.f};
    if (tid < TT) {
        int b = tid >> 1;
        float pos = g_sTop[tid * BB + b];
        float pe = __expf(10.f * pos);
        float ns = 0.f;
        for (int q = 0; q < BB; q++)
            if (q != b) ns += __expf(10.f * g_sTop[tid * BB + q]);
        vals[0] = -(10.f * pos - logf(pe + ns));
        vals[1] = -(10.f * pos - logf(pe + (totQ[b] - posQ[b])));
        float inv0 = 1.f / fmaxf(sqrtf(g_norm2k[2 * b]), 1e-12f);
        float inv1 = 1.f / fmaxf(sqrtf(g_norm2k[2 * b + 1]), 1e-12f);
        float crossn = g_cross[b] * inv0 * inv1;
        float invt = (tid & 1) ? inv1 : inv0;
        float selfn = g_norm2k[tid] * invt * invt;
        float nI = negI[tid];
        vals[2] = -(10.f * selfn  - logf(__expf(10.f * selfn)  + nI))
                + -(10.f * crossn - logf(__expf(10.f * crossn) + nI));
        float posq = g_qs[b * TT + tid];
        float nsq = 0.f;
        for (int t2 = 0; t2 < TT; t2++)
            if ((t2 >> 1) != b) nsq += __expf(10.f * g_qs[b * TT + t2]);
        vals[3] = -(10.f * posq - logf(__expf(10.f * posq) + nsq));
    }
    const float divi[4] = {128.f, 128.f, 256.f, 128.f};
    for (int m = 0; m < 4; m++) {
        red[tid] = vals[m];
        __syncthreads();
        for (int s = 128; s > 0; s >>= 1) {
            if (tid < s) red[tid] += red[tid + s];
            __syncthreads();
        }
        if (tid == 0) out[m] = red[0] / divi[m];
        __syncthreads();
    }
}

// ---------------- launch (k_main 4th for the profile window) ----------------
extern "C" void kernel_launch(void* const* d_in, const int* in_sizes, int n_in,
                              void* d_out, int out_size) {
    const float* vid    = (const float*)d_in[0];
    const float* qf     = (const float*)d_in[1];
    const float* sf     = (const float*)d_in[2];
    const float* iou2d  = (const float*)d_in[3];
    const float* iou2ds = (const float*)d_in[4];
    (void)in_sizes; (void)n_in; (void)out_size;

    cudaFuncSetAttribute(k_main, cudaFuncAttributeMaxDynamicSharedMemorySize, DYN_SMEM);

    k_topk  <<<TT, 256>>>(iou2ds);
    k_norms <<<BB + TT, 256>>>(qf, sf);
    k_qs    <<<BB, 256>>>();
    k_main  <<<dim3(NTILE, BB), 256, DYN_SMEM>>>(vid, iou2d);
    k_reduce<<<BB, 256>>>();
    k_final <<<1, 256>>>((float*)d_out);
}